// round 1
// baseline (speedup 1.0000x reference)
#include <cuda_runtime.h>
#include <math.h>

// ---------------- problem constants ----------------
#define Bdim 32
#define Sdim 512
#define Hdim 768
#define Ndim 4096
#define Edim 131072
#define Pdim 65536
#define ETOT (Edim + Ndim)       // 135168 (self loops appended)
#define H1 4
#define C1 128
#define F1 (H1*C1)               // 512
#define C2 64
#define NREL 6
#define RHID 256
#define NERH 256
#define NERL 9
#define SLOPE 0.2f
#define LNEPS 1e-5f
#define NER_OUT_ELEMS (Bdim*Sdim*NERL)   // 147456

// ---------------- device scratch ----------------
__device__ float g_x0[Ndim*Hdim];      // pooled entity features [4096,768]
__device__ float g_h1[Ndim*F1];        // GAT1 linear out
__device__ float g_out1[Ndim*F1];      // GAT1 aggregated + relu
__device__ float g_h2[Ndim*C2];        // GAT2 linear out
__device__ float g_x2[Ndim*C2];        // GAT2 aggregated
__device__ float g_es1[Ndim*H1], g_ed1[Ndim*H1];
__device__ float g_es2[Ndim],    g_ed2[Ndim];
__device__ int   g_deg[Ndim], g_cursor[Ndim], g_rowstart[Ndim+1];
__device__ int   g_csr[ETOT];
__device__ float g_tb[12*Ndim*RHID];   // per-node per-relation top/bottom contributions

// ---------------- helpers ----------------
__device__ __forceinline__ float warpSum(float v){
    #pragma unroll
    for(int o=16;o;o>>=1) v += __shfl_xor_sync(0xffffffffu, v, o);
    return v;
}
__device__ __forceinline__ float warpMax(float v){
    #pragma unroll
    for(int o=16;o;o>>=1) v = fmaxf(v, __shfl_xor_sync(0xffffffffu, v, o));
    return v;
}

// ---------------- 1) entity span mean pooling ----------------
__global__ void k_span_pool(const float* __restrict__ seq,
                            const int* __restrict__ est, const int* __restrict__ elen,
                            const int* __restrict__ ebat){
    int n = blockIdx.x;
    int b = ebat[n], st = est[n], len = elen[n];
    const float* base = seq + ((size_t)b*Sdim + st)*Hdim + threadIdx.x*4;
    float4 acc = make_float4(0.f,0.f,0.f,0.f);
    for(int r=0; r<=len; r++){
        float4 t = *reinterpret_cast<const float4*>(base + (size_t)r*Hdim);
        acc.x += t.x; acc.y += t.y; acc.z += t.z; acc.w += t.w;
    }
    float inv = 1.0f/(float)(len+1);
    acc.x*=inv; acc.y*=inv; acc.z*=inv; acc.w*=inv;
    *reinterpret_cast<float4*>(&g_x0[(size_t)n*Hdim + threadIdx.x*4]) = acc;
}

// ---------------- generic 32x256 FFMA GEMM (C = A @ B), batched over z ----------------
// grid: (N/256, M/32, Z), block 256. lda/ldb/ldc in floats.
__global__ void k_gemm32x256(const float* __restrict__ A, int lda,
                             const float* __restrict__ B, int ldb, long bStrideZ,
                             float* __restrict__ C, int ldc, long cStrideZ, int K){
    __shared__ float sA[32*16];
    __shared__ float sB[16*256];
    int tid = threadIdx.x, tx = tid & 31, ty = tid >> 5;
    int n0 = blockIdx.x * 256;
    int m0 = blockIdx.y * 32;
    const float* Ab = A + (size_t)m0*lda;
    const float* Bb = B + (size_t)blockIdx.z*bStrideZ + n0;
    float*       Cb = C + (size_t)blockIdx.z*cStrideZ + (size_t)m0*ldc + n0;

    float acc[4][8];
    #pragma unroll
    for(int i=0;i<4;i++)
        #pragma unroll
        for(int j=0;j<8;j++) acc[i][j]=0.f;

    for(int k0=0;k0<K;k0+=16){
        { // sA load: 32x16 via float2
            int row = tid >> 3; int kk = (tid & 7)*2;
            float2 t = *reinterpret_cast<const float2*>(Ab + (size_t)row*lda + k0 + kk);
            sA[row*16+kk]   = t.x;
            sA[row*16+kk+1] = t.y;
        }
        #pragma unroll
        for(int j=0;j<4;j++){ // sB load: 16x256 via float4
            int idx = tid + j*256;
            int row = idx >> 6; int c4 = (idx & 63);
            float4 t = *reinterpret_cast<const float4*>(Bb + (size_t)(k0+row)*ldb + c4*4);
            *reinterpret_cast<float4*>(&sB[row*256 + c4*4]) = t;
        }
        __syncthreads();
        #pragma unroll
        for(int kk=0;kk<16;kk++){
            float a0 = sA[(ty*4+0)*16+kk];
            float a1 = sA[(ty*4+1)*16+kk];
            float a2 = sA[(ty*4+2)*16+kk];
            float a3 = sA[(ty*4+3)*16+kk];
            #pragma unroll
            for(int j=0;j<8;j++){
                float b = sB[kk*256 + tx + 32*j];
                acc[0][j] += a0*b; acc[1][j] += a1*b;
                acc[2][j] += a2*b; acc[3][j] += a3*b;
            }
        }
        __syncthreads();
    }
    #pragma unroll
    for(int i=0;i<4;i++)
        #pragma unroll
        for(int j=0;j<8;j++)
            Cb[(size_t)(ty*4+i)*ldc + tx + 32*j] = acc[i][j];
}

// ---------------- GAT attention coefficients e_src/e_dst ----------------
template<int HEADS,int C>
__global__ void k_attn_coef(const float* __restrict__ h,
                            const float* __restrict__ a_src, const float* __restrict__ a_dst,
                            float* __restrict__ es, float* __restrict__ ed){
    const int F = HEADS*C;
    int n = blockIdx.x;
    int hh = threadIdx.x >> 5, lane = threadIdx.x & 31;
    float s1 = 0.f, s2 = 0.f;
    #pragma unroll
    for(int i=0;i<C/32;i++){
        float v = h[(size_t)n*F + hh*C + lane + 32*i];
        s1 += v * a_src[hh*C + lane + 32*i];
        s2 += v * a_dst[hh*C + lane + 32*i];
    }
    s1 = warpSum(s1); s2 = warpSum(s2);
    if(lane==0){ es[n*HEADS+hh] = s1; ed[n*HEADS+hh] = s2; }
}

// ---------------- CSR build ----------------
__global__ void k_csr_init(){
    int i = blockIdx.x*blockDim.x + threadIdx.x;
    if(i < Ndim){ g_deg[i]=0; g_cursor[i]=0; }
}
__global__ void k_csr_count(const int* __restrict__ ei){
    int e = blockIdx.x*blockDim.x + threadIdx.x;
    if(e >= ETOT) return;
    int dst = (e < Edim) ? ei[Edim + e] : (e - Edim);
    atomicAdd(&g_deg[dst], 1);
}
__global__ void k_csr_scan(){
    __shared__ int s[1024];
    int t = threadIdx.x;
    int v0 = g_deg[t*4+0], v1 = g_deg[t*4+1], v2 = g_deg[t*4+2], v3 = g_deg[t*4+3];
    int c0 = v0, c1 = c0+v1, c2 = c1+v2, c3 = c2+v3;
    s[t] = c3;
    __syncthreads();
    for(int off=1; off<1024; off<<=1){
        int x = (t >= off) ? s[t-off] : 0;
        __syncthreads();
        s[t] += x;
        __syncthreads();
    }
    int excl = s[t] - c3;
    g_rowstart[t*4+1] = excl + c0;
    g_rowstart[t*4+2] = excl + c1;
    g_rowstart[t*4+3] = excl + c2;
    g_rowstart[t*4+4] = excl + c3;
    if(t==0) g_rowstart[0] = 0;
}
__global__ void k_csr_scatter(const int* __restrict__ ei){
    int e = blockIdx.x*blockDim.x + threadIdx.x;
    if(e >= ETOT) return;
    int src, dst;
    if(e < Edim){ src = ei[e]; dst = ei[Edim + e]; }
    else        { src = e - Edim; dst = src; }
    int pos = g_rowstart[dst] + atomicAdd(&g_cursor[dst], 1);
    g_csr[pos] = src;
}

// ---------------- GAT softmax + aggregation (per dst node, warp per head) ----------------
template<int HEADS,int C,bool RELU>
__global__ void k_gat_agg(const float* __restrict__ h,
                          const float* __restrict__ es, const float* __restrict__ ed,
                          const float* __restrict__ bias, float* __restrict__ out){
    const int F = HEADS*C;
    int d = blockIdx.x;
    int hh = threadIdx.x >> 5, lane = threadIdx.x & 31;
    int rs = g_rowstart[d], re = g_rowstart[d+1];
    float edv = ed[d*HEADS + hh];

    float m = -1e30f;
    for(int e=rs+lane; e<re; e+=32){
        int s = g_csr[e];
        float t = es[s*HEADS+hh] + edv;
        t = (t > 0.f) ? t : SLOPE*t;
        m = fmaxf(m, t);
    }
    m = warpMax(m);

    float den = 0.f;
    for(int e=rs+lane; e<re; e+=32){
        int s = g_csr[e];
        float t = es[s*HEADS+hh] + edv;
        t = (t > 0.f) ? t : SLOPE*t;
        den += __expf(t - m);
    }
    den = warpSum(den);
    float inv = 1.0f/den;

    float acc[C/32];
    #pragma unroll
    for(int i=0;i<C/32;i++) acc[i]=0.f;

    for(int e=rs; e<re; e++){
        int s = g_csr[e];
        float t = es[s*HEADS+hh] + edv;
        t = (t > 0.f) ? t : SLOPE*t;
        float w = __expf(t - m)*inv;
        const float* hp = h + (size_t)s*F + hh*C + lane;
        #pragma unroll
        for(int i=0;i<C/32;i++) acc[i] += w*hp[32*i];
    }
    #pragma unroll
    for(int i=0;i<C/32;i++){
        float v = acc[i] + bias[hh*C + lane + 32*i];
        if(RELU) v = fmaxf(v, 0.f);
        out[(size_t)d*F + hh*C + lane + 32*i] = v;
    }
}

// ---------------- small GEMM for layer2 linear: h2 = out1 @ W2 ----------------
__global__ void k_gemm2(const float* __restrict__ A, const float* __restrict__ W){
    __shared__ float sA[F1];
    int m = blockIdx.x;
    for(int k=threadIdx.x; k<F1; k+=64) sA[k] = A[(size_t)m*F1 + k];
    __syncthreads();
    int col = threadIdx.x;
    float acc = 0.f;
    #pragma unroll 8
    for(int k=0;k<F1;k++) acc += sA[k]*W[(size_t)k*C2 + col];
    g_h2[(size_t)m*C2 + col] = acc;
}

// ---------------- fused NER head: relu(seq @ W1 + b1) @ W2 + b2 ----------------
__global__ void k_ner(const float* __restrict__ A,
                      const float* __restrict__ W1, const float* __restrict__ b1,
                      const float* __restrict__ W2s, const float* __restrict__ b2,
                      float* __restrict__ out){
    __shared__ float pool[2304 + 8192];
    float* sW2 = pool;                 // 256x9
    float* sA  = pool + 2304;          // 32x16 (GEMM phase)
    float* sB  = pool + 2304 + 512;    // 16x256 (GEMM phase)
    float* hid = pool + 2304;          // 32x256 (epilogue, aliases sA/sB)

    int tid = threadIdx.x, tx = tid & 31, ty = tid >> 5;
    for(int j=tid; j<2304; j+=256) sW2[j] = W2s[j];

    int m0 = blockIdx.x * 32;
    const float* Ab = A + (size_t)m0*Hdim;

    float acc[4][8];
    #pragma unroll
    for(int i=0;i<4;i++)
        #pragma unroll
        for(int j=0;j<8;j++) acc[i][j]=0.f;

    for(int k0=0;k0<Hdim;k0+=16){
        {
            int row = tid >> 3; int kk = (tid & 7)*2;
            float2 t = *reinterpret_cast<const float2*>(Ab + (size_t)row*Hdim + k0 + kk);
            sA[row*16+kk] = t.x; sA[row*16+kk+1] = t.y;
        }
        #pragma unroll
        for(int j=0;j<4;j++){
            int idx = tid + j*256;
            int row = idx >> 6; int c4 = (idx & 63);
            float4 t = *reinterpret_cast<const float4*>(W1 + (size_t)(k0+row)*NERH + c4*4);
            *reinterpret_cast<float4*>(&sB[row*256 + c4*4]) = t;
        }
        __syncthreads();
        #pragma unroll
        for(int kk=0;kk<16;kk++){
            float a0 = sA[(ty*4+0)*16+kk];
            float a1 = sA[(ty*4+1)*16+kk];
            float a2 = sA[(ty*4+2)*16+kk];
            float a3 = sA[(ty*4+3)*16+kk];
            #pragma unroll
            for(int j=0;j<8;j++){
                float b = sB[kk*256 + tx + 32*j];
                acc[0][j] += a0*b; acc[1][j] += a1*b;
                acc[2][j] += a2*b; acc[3][j] += a3*b;
            }
        }
        __syncthreads();
    }
    // bias + relu -> hid (aliases GEMM smem; safe: last sync above)
    #pragma unroll
    for(int i=0;i<4;i++)
        #pragma unroll
        for(int j=0;j<8;j++){
            int col = tx + 32*j;
            float v = acc[i][j] + b1[col];
            hid[(ty*4+i)*256 + col] = fmaxf(v, 0.f);
        }
    __syncthreads();
    // second stage: 256 -> 9 per row (warp ty handles rows ty*4..ty*4+3)
    for(int rr=0;rr<4;rr++){
        int row = ty*4 + rr;
        float o[NERL];
        #pragma unroll
        for(int c=0;c<NERL;c++) o[c]=0.f;
        #pragma unroll
        for(int t=0;t<8;t++){
            int k = tx + 32*t;
            float hv = hid[row*256 + k];
            #pragma unroll
            for(int c=0;c<NERL;c++) o[c] += hv * sW2[k*NERL + c];
        }
        #pragma unroll
        for(int c=0;c<NERL;c++){
            float s = warpSum(o[c]);
            if(tx==0) out[(size_t)(m0+row)*NERL + c] = s + b2[c];
        }
    }
}

// ---------------- fused relation head (per pair): LN + relu + dot ----------------
__global__ void k_rel(const int* __restrict__ pidx,
                      const float* __restrict__ relb1, const float* __restrict__ lng,
                      const float* __restrict__ lnb, const float* __restrict__ relW2,
                      const float* __restrict__ relb2, float* __restrict__ out){
    __shared__ float sb1[256], sg[256], sbb[256], sw2[256];
    int r = blockIdx.y;
    int tid = threadIdx.x;
    sb1[tid] = relb1[r*256+tid];
    sg[tid]  = lng[r*256+tid];
    sbb[tid] = lnb[r*256+tid];
    sw2[tid] = relW2[r*256+tid];
    __syncthreads();

    int w = tid >> 5, lane = tid & 31;
    int p = blockIdx.x*8 + w;
    int i = pidx[p*2], j = pidx[p*2+1];
    const float* ti = g_tb + ((size_t)(r*2+0)*Ndim + i)*RHID;
    const float* tj = g_tb + ((size_t)(r*2+1)*Ndim + j)*RHID;

    float v[8]; float s1 = 0.f, s2 = 0.f;
    #pragma unroll
    for(int t=0;t<8;t++){
        int k = lane + 32*t;
        float x = ti[k] + tj[k] + sb1[k];
        v[t] = x; s1 += x; s2 += x*x;
    }
    s1 = warpSum(s1); s2 = warpSum(s2);
    float mu  = s1 * (1.0f/256.0f);
    float var = s2 * (1.0f/256.0f) - mu*mu;
    float rinv = rsqrtf(var + LNEPS);

    float acc = 0.f;
    #pragma unroll
    for(int t=0;t<8;t++){
        int k = lane + 32*t;
        float x = (v[t]-mu)*rinv*sg[k] + sbb[k];
        x = fmaxf(x, 0.f);
        acc += x * sw2[k];
    }
    acc = warpSum(acc);
    if(lane==0) out[(size_t)r*Pdim + p] = acc + relb2[r];
}

// ---------------- launch ----------------
extern "C" void kernel_launch(void* const* d_in, const int* in_sizes, int n_in,
                              void* d_out, int out_size){
    const float* seq     = (const float*)d_in[0];
    const int*   est     = (const int*)  d_in[1];
    const int*   elen    = (const int*)  d_in[2];
    const int*   ebat    = (const int*)  d_in[3];
    const int*   ei      = (const int*)  d_in[4];
    const int*   pidx    = (const int*)  d_in[5];
    const float* W1      = (const float*)d_in[6];
    const float* a_src1  = (const float*)d_in[7];
    const float* a_dst1  = (const float*)d_in[8];
    const float* b1      = (const float*)d_in[9];
    const float* W2      = (const float*)d_in[10];
    const float* a_src2  = (const float*)d_in[11];
    const float* a_dst2  = (const float*)d_in[12];
    const float* b2      = (const float*)d_in[13];
    const float* relW1   = (const float*)d_in[14];
    const float* relb1   = (const float*)d_in[15];
    const float* ln_g    = (const float*)d_in[16];
    const float* ln_b    = (const float*)d_in[17];
    const float* relW2   = (const float*)d_in[18];
    const float* relb2   = (const float*)d_in[19];
    const float* nerW1   = (const float*)d_in[20];
    const float* nerb1   = (const float*)d_in[21];
    const float* nerW2   = (const float*)d_in[22];
    const float* nerb2   = (const float*)d_in[23];
    float* out = (float*)d_out;

    float* g_x0_p;   cudaGetSymbolAddress((void**)&g_x0_p,   g_x0);
    float* g_h1_p;   cudaGetSymbolAddress((void**)&g_h1_p,   g_h1);
    float* g_out1_p; cudaGetSymbolAddress((void**)&g_out1_p, g_out1);
    float* g_h2_p;   cudaGetSymbolAddress((void**)&g_h2_p,   g_h2);
    float* g_x2_p;   cudaGetSymbolAddress((void**)&g_x2_p,   g_x2);
    float* g_es1_p;  cudaGetSymbolAddress((void**)&g_es1_p,  g_es1);
    float* g_ed1_p;  cudaGetSymbolAddress((void**)&g_ed1_p,  g_ed1);
    float* g_es2_p;  cudaGetSymbolAddress((void**)&g_es2_p,  g_es2);
    float* g_ed2_p;  cudaGetSymbolAddress((void**)&g_ed2_p,  g_ed2);
    float* g_tb_p;   cudaGetSymbolAddress((void**)&g_tb_p,   g_tb);

    // NER head (independent of graph path)
    k_ner<<<Bdim*Sdim/32, 256>>>(seq, nerW1, nerb1, nerW2, nerb2, out);

    // entity pooling
    k_span_pool<<<Ndim, 192>>>(seq, est, elen, ebat);

    // GAT layer 1 linear: h1 = x0 @ W1  (4096x768x512)
    k_gemm32x256<<<dim3(F1/256, Ndim/32, 1), 256>>>(g_x0_p, Hdim, W1, F1, 0, g_h1_p, F1, 0, Hdim);

    // CSR build (shared by both layers)
    k_csr_init<<<(Ndim+255)/256, 256>>>();
    k_csr_count<<<(ETOT+255)/256, 256>>>(ei);
    k_csr_scan<<<1, 1024>>>();
    k_csr_scatter<<<(ETOT+255)/256, 256>>>(ei);

    // GAT layer 1 attention + aggregation (+bias, relu)
    k_attn_coef<H1, C1><<<Ndim, 128>>>(g_h1_p, a_src1, a_dst1, g_es1_p, g_ed1_p);
    k_gat_agg<H1, C1, true><<<Ndim, 128>>>(g_h1_p, g_es1_p, g_ed1_p, b1, g_out1_p);

    // GAT layer 2
    k_gemm2<<<Ndim, 64>>>(g_out1_p, W2);
    k_attn_coef<1, C2><<<Ndim, 32>>>(g_h2_p, a_src2, a_dst2, g_es2_p, g_ed2_p);
    k_gat_agg<1, C2, false><<<Ndim, 32>>>(g_h2_p, g_es2_p, g_ed2_p, b2, g_x2_p);

    // per-node relation contributions: tb[z] = x2 @ relW1[z*64:(z+1)*64]  (z = r*2 + half)
    k_gemm32x256<<<dim3(1, Ndim/32, 12), 256>>>(g_x2_p, C2, relW1, RHID, (long)64*RHID,
                                                g_tb_p, RHID, (long)Ndim*RHID, C2);

    // fused relation classifier per pair
    k_rel<<<dim3(Pdim/8, NREL), 256>>>(pidx, relb1, ln_g, ln_b, relW2, relb2, out + NER_OUT_ELEMS);
}

// round 2
// speedup vs baseline: 1.1334x; 1.1334x over previous
#include <cuda_runtime.h>
#include <math.h>

// ---------------- problem constants ----------------
#define Bdim 32
#define Sdim 512
#define Hdim 768
#define Ndim 4096
#define Edim 131072
#define Pdim 65536
#define ETOT (Edim + Ndim)       // 135168 (self loops appended)
#define H1 4
#define C1 128
#define F1 (H1*C1)               // 512
#define C2 64
#define NREL 6
#define RHID 256
#define NERH 256
#define NERL 9
#define SLOPE 0.2f
#define LNEPS 1e-5f
#define NER_OUT_ELEMS (Bdim*Sdim*NERL)   // 147456
#define NERROWS (Bdim*Sdim)              // 16384

// ---------------- device scratch ----------------
__device__ float g_x0[Ndim*Hdim];      // pooled entity features [4096,768]
__device__ float g_h1[Ndim*F1];        // GAT1 linear out
__device__ float g_out1[Ndim*F1];      // GAT1 aggregated + relu
__device__ float g_h2[Ndim*C2];        // GAT2 linear out
__device__ float g_x2[Ndim*C2];        // GAT2 aggregated
__device__ float g_es1[Ndim*H1], g_ed1[Ndim*H1];
__device__ float g_es2[Ndim],    g_ed2[Ndim];
__device__ int   g_deg[Ndim], g_cursor[Ndim], g_rowstart[Ndim+1];
__device__ int   g_csr[ETOT];
__device__ float g_tb[12*Ndim*RHID];   // per-node per-relation top/bottom contributions
__device__ float g_nerhid[NERROWS*NERH]; // NER hidden activations

// ---------------- helpers ----------------
__device__ __forceinline__ float warpSum(float v){
    #pragma unroll
    for(int o=16;o;o>>=1) v += __shfl_xor_sync(0xffffffffu, v, o);
    return v;
}
__device__ __forceinline__ float warpMax(float v){
    #pragma unroll
    for(int o=16;o;o>>=1) v = fmaxf(v, __shfl_xor_sync(0xffffffffu, v, o));
    return v;
}
// packed dual-FMA (SASS FFMA2) — only reachable via PTX f32x2
__device__ __forceinline__ void fma2(unsigned long long &acc, unsigned long long a, unsigned long long b){
    asm("fma.rn.f32x2 %0, %1, %2, %0;" : "+l"(acc) : "l"(a), "l"(b));
}
__device__ __forceinline__ unsigned long long pack2(float x, float y){
    unsigned long long r; asm("mov.b64 %0, {%1, %2};" : "=l"(r) : "f"(x), "f"(y)); return r;
}
__device__ __forceinline__ void unpack2(unsigned long long v, float &x, float &y){
    asm("mov.b64 {%0, %1}, %2;" : "=f"(x), "=f"(y) : "l"(v));
}

// ---------------- 1) entity span mean pooling ----------------
__global__ void k_span_pool(const float* __restrict__ seq,
                            const int* __restrict__ est, const int* __restrict__ elen,
                            const int* __restrict__ ebat){
    int n = blockIdx.x;
    int b = ebat[n], st = est[n], len = elen[n];
    const float* base = seq + ((size_t)b*Sdim + st)*Hdim + threadIdx.x*4;
    float4 acc = make_float4(0.f,0.f,0.f,0.f);
    for(int r=0; r<=len; r++){
        float4 t = *reinterpret_cast<const float4*>(base + (size_t)r*Hdim);
        acc.x += t.x; acc.y += t.y; acc.z += t.z; acc.w += t.w;
    }
    float inv = 1.0f/(float)(len+1);
    acc.x*=inv; acc.y*=inv; acc.z*=inv; acc.w*=inv;
    *reinterpret_cast<float4*>(&g_x0[(size_t)n*Hdim + threadIdx.x*4]) = acc;
}

// ---------------- 128x128 tile FFMA2 GEMM: C = op(A @ B [+bias]) ----------------
// grid (N/128, M/128, Z), block 256 (16x16 threads, 8x8 per thread), K % 16 == 0
#define SASTR 132
template<bool BIAS, bool RELU>
__global__ void __launch_bounds__(256) k_gemm128(
        const float* __restrict__ A, int lda,
        const float* __restrict__ B, int ldb, long bStrideZ,
        const float* __restrict__ bias,
        float* __restrict__ C, int ldc, long cStrideZ, int K){
    __shared__ float sAT[16*SASTR];   // transposed A panel [k][m]
    __shared__ float sB[16*128];      // B panel [k][n]

    int tid = threadIdx.x;
    int tcol = tid & 15, trow = tid >> 4;
    int n0 = blockIdx.x * 128;
    int m0 = blockIdx.y * 128;
    const float* Ab = A + (size_t)m0*lda;
    const float* Bb = B + (size_t)blockIdx.z*bStrideZ + n0;
    float*       Cb = C + (size_t)blockIdx.z*cStrideZ + (size_t)m0*ldc + n0;

    unsigned long long acc[8][4];
    const unsigned long long z2 = pack2(0.f, 0.f);
    #pragma unroll
    for(int i=0;i<8;i++)
        #pragma unroll
        for(int j=0;j<4;j++) acc[i][j] = z2;

    for(int k0=0;k0<K;k0+=16){
        // load A tile 128x16 and store transposed
        #pragma unroll
        for(int i=0;i<2;i++){
            int pos = tid + i*256;          // 512 float4 slots
            int row = pos >> 2, c4 = pos & 3;
            float4 t = *reinterpret_cast<const float4*>(Ab + (size_t)row*lda + k0 + c4*4);
            sAT[(c4*4+0)*SASTR + row] = t.x;
            sAT[(c4*4+1)*SASTR + row] = t.y;
            sAT[(c4*4+2)*SASTR + row] = t.z;
            sAT[(c4*4+3)*SASTR + row] = t.w;
        }
        // load B tile 16x128
        #pragma unroll
        for(int i=0;i<2;i++){
            int pos = tid + i*256;          // 512 float4 slots
            int row = pos >> 5, c4 = pos & 31;
            float4 t = *reinterpret_cast<const float4*>(Bb + (size_t)(k0+row)*ldb + c4*4);
            *reinterpret_cast<float4*>(&sB[row*128 + c4*4]) = t;
        }
        __syncthreads();
        #pragma unroll
        for(int kk=0;kk<16;kk++){
            float4 a0 = *reinterpret_cast<const float4*>(&sAT[kk*SASTR + trow*8]);
            float4 a1 = *reinterpret_cast<const float4*>(&sAT[kk*SASTR + trow*8 + 4]);
            float4 b0 = *reinterpret_cast<const float4*>(&sB[kk*128 + tcol*8]);
            float4 b1 = *reinterpret_cast<const float4*>(&sB[kk*128 + tcol*8 + 4]);
            unsigned long long bp0 = pack2(b0.x, b0.y);
            unsigned long long bp1 = pack2(b0.z, b0.w);
            unsigned long long bp2 = pack2(b1.x, b1.y);
            unsigned long long bp3 = pack2(b1.z, b1.w);
            unsigned long long ad;
            ad = pack2(a0.x, a0.x);
            fma2(acc[0][0],ad,bp0); fma2(acc[0][1],ad,bp1); fma2(acc[0][2],ad,bp2); fma2(acc[0][3],ad,bp3);
            ad = pack2(a0.y, a0.y);
            fma2(acc[1][0],ad,bp0); fma2(acc[1][1],ad,bp1); fma2(acc[1][2],ad,bp2); fma2(acc[1][3],ad,bp3);
            ad = pack2(a0.z, a0.z);
            fma2(acc[2][0],ad,bp0); fma2(acc[2][1],ad,bp1); fma2(acc[2][2],ad,bp2); fma2(acc[2][3],ad,bp3);
            ad = pack2(a0.w, a0.w);
            fma2(acc[3][0],ad,bp0); fma2(acc[3][1],ad,bp1); fma2(acc[3][2],ad,bp2); fma2(acc[3][3],ad,bp3);
            ad = pack2(a1.x, a1.x);
            fma2(acc[4][0],ad,bp0); fma2(acc[4][1],ad,bp1); fma2(acc[4][2],ad,bp2); fma2(acc[4][3],ad,bp3);
            ad = pack2(a1.y, a1.y);
            fma2(acc[5][0],ad,bp0); fma2(acc[5][1],ad,bp1); fma2(acc[5][2],ad,bp2); fma2(acc[5][3],ad,bp3);
            ad = pack2(a1.z, a1.z);
            fma2(acc[6][0],ad,bp0); fma2(acc[6][1],ad,bp1); fma2(acc[6][2],ad,bp2); fma2(acc[6][3],ad,bp3);
            ad = pack2(a1.w, a1.w);
            fma2(acc[7][0],ad,bp0); fma2(acc[7][1],ad,bp1); fma2(acc[7][2],ad,bp2); fma2(acc[7][3],ad,bp3);
        }
        __syncthreads();
    }
    // epilogue
    #pragma unroll
    for(int i=0;i<8;i++){
        int m = trow*8 + i;
        float v[8];
        unpack2(acc[i][0], v[0], v[1]);
        unpack2(acc[i][1], v[2], v[3]);
        unpack2(acc[i][2], v[4], v[5]);
        unpack2(acc[i][3], v[6], v[7]);
        #pragma unroll
        for(int j=0;j<8;j++){
            if(BIAS) v[j] += bias[n0 + tcol*8 + j];
            if(RELU) v[j] = fmaxf(v[j], 0.f);
        }
        float4* cp = reinterpret_cast<float4*>(Cb + (size_t)m*ldc + tcol*8);
        cp[0] = make_float4(v[0],v[1],v[2],v[3]);
        cp[1] = make_float4(v[4],v[5],v[6],v[7]);
    }
}

// ---------------- NER stage 2: out = hid @ W2 + b2 (256 -> 9) ----------------
__global__ void k_ner2(const float* __restrict__ hid, const float* __restrict__ W2s,
                       const float* __restrict__ b2, float* __restrict__ out){
    __shared__ float sW2[NERH*NERL];
    int tid = threadIdx.x;
    for(int j=tid; j<NERH*NERL; j+=256) sW2[j] = W2s[j];
    __syncthreads();
    int w = tid >> 5, lane = tid & 31;
    int row = blockIdx.x*8 + w;
    const float* hp = hid + (size_t)row*NERH;
    float o[NERL];
    #pragma unroll
    for(int c=0;c<NERL;c++) o[c]=0.f;
    #pragma unroll
    for(int t=0;t<8;t++){
        int k = lane + 32*t;
        float hv = hp[k];
        #pragma unroll
        for(int c=0;c<NERL;c++) o[c] += hv * sW2[k*NERL + c];
    }
    #pragma unroll
    for(int c=0;c<NERL;c++){
        float s = warpSum(o[c]);
        if(lane==0) out[(size_t)row*NERL + c] = s + b2[c];
    }
}

// ---------------- GAT attention coefficients e_src/e_dst ----------------
template<int HEADS,int C>
__global__ void k_attn_coef(const float* __restrict__ h,
                            const float* __restrict__ a_src, const float* __restrict__ a_dst,
                            float* __restrict__ es, float* __restrict__ ed){
    const int F = HEADS*C;
    int n = blockIdx.x;
    int hh = threadIdx.x >> 5, lane = threadIdx.x & 31;
    float s1 = 0.f, s2 = 0.f;
    #pragma unroll
    for(int i=0;i<C/32;i++){
        float v = h[(size_t)n*F + hh*C + lane + 32*i];
        s1 += v * a_src[hh*C + lane + 32*i];
        s2 += v * a_dst[hh*C + lane + 32*i];
    }
    s1 = warpSum(s1); s2 = warpSum(s2);
    if(lane==0){ es[n*HEADS+hh] = s1; ed[n*HEADS+hh] = s2; }
}

// ---------------- CSR build ----------------
__global__ void k_csr_init(){
    int i = blockIdx.x*blockDim.x + threadIdx.x;
    if(i < Ndim){ g_deg[i]=0; g_cursor[i]=0; }
}
__global__ void k_csr_count(const int* __restrict__ ei){
    int e = blockIdx.x*blockDim.x + threadIdx.x;
    if(e >= ETOT) return;
    int dst = (e < Edim) ? ei[Edim + e] : (e - Edim);
    atomicAdd(&g_deg[dst], 1);
}
__global__ void k_csr_scan(){
    __shared__ int s[1024];
    int t = threadIdx.x;
    int v0 = g_deg[t*4+0], v1 = g_deg[t*4+1], v2 = g_deg[t*4+2], v3 = g_deg[t*4+3];
    int c0 = v0, c1 = c0+v1, c2 = c1+v2, c3 = c2+v3;
    s[t] = c3;
    __syncthreads();
    for(int off=1; off<1024; off<<=1){
        int x = (t >= off) ? s[t-off] : 0;
        __syncthreads();
        s[t] += x;
        __syncthreads();
    }
    int excl = s[t] - c3;
    g_rowstart[t*4+1] = excl + c0;
    g_rowstart[t*4+2] = excl + c1;
    g_rowstart[t*4+3] = excl + c2;
    g_rowstart[t*4+4] = excl + c3;
    if(t==0) g_rowstart[0] = 0;
}
__global__ void k_csr_scatter(const int* __restrict__ ei){
    int e = blockIdx.x*blockDim.x + threadIdx.x;
    if(e >= ETOT) return;
    int src, dst;
    if(e < Edim){ src = ei[e]; dst = ei[Edim + e]; }
    else        { src = e - Edim; dst = src; }
    int pos = g_rowstart[dst] + atomicAdd(&g_cursor[dst], 1);
    g_csr[pos] = src;
}

// ---------------- GAT softmax + aggregation (per dst node, warp per head) ----------------
template<int HEADS,int C,bool RELU>
__global__ void k_gat_agg(const float* __restrict__ h,
                          const float* __restrict__ es, const float* __restrict__ ed,
                          const float* __restrict__ bias, float* __restrict__ out){
    const int F = HEADS*C;
    int d = blockIdx.x;
    int hh = threadIdx.x >> 5, lane = threadIdx.x & 31;
    int rs = g_rowstart[d], re = g_rowstart[d+1];
    float edv = ed[d*HEADS + hh];

    float m = -1e30f;
    for(int e=rs+lane; e<re; e+=32){
        int s = g_csr[e];
        float t = es[s*HEADS+hh] + edv;
        t = (t > 0.f) ? t : SLOPE*t;
        m = fmaxf(m, t);
    }
    m = warpMax(m);

    float den = 0.f;
    for(int e=rs+lane; e<re; e+=32){
        int s = g_csr[e];
        float t = es[s*HEADS+hh] + edv;
        t = (t > 0.f) ? t : SLOPE*t;
        den += __expf(t - m);
    }
    den = warpSum(den);
    float inv = 1.0f/den;

    float acc[C/32];
    #pragma unroll
    for(int i=0;i<C/32;i++) acc[i]=0.f;

    for(int e=rs; e<re; e++){
        int s = g_csr[e];
        float t = es[s*HEADS+hh] + edv;
        t = (t > 0.f) ? t : SLOPE*t;
        float w = __expf(t - m)*inv;
        const float* hp = h + (size_t)s*F + hh*C + lane;
        #pragma unroll
        for(int i=0;i<C/32;i++) acc[i] += w*hp[32*i];
    }
    #pragma unroll
    for(int i=0;i<C/32;i++){
        float v = acc[i] + bias[hh*C + lane + 32*i];
        if(RELU) v = fmaxf(v, 0.f);
        out[(size_t)d*F + hh*C + lane + 32*i] = v;
    }
}

// ---------------- small GEMM for layer2 linear: h2 = out1 @ W2 ----------------
__global__ void k_gemm2(const float* __restrict__ A, const float* __restrict__ W){
    __shared__ float sA[F1];
    int m = blockIdx.x;
    for(int k=threadIdx.x; k<F1; k+=64) sA[k] = A[(size_t)m*F1 + k];
    __syncthreads();
    int col = threadIdx.x;
    float acc = 0.f;
    #pragma unroll 8
    for(int k=0;k<F1;k++) acc += sA[k]*W[(size_t)k*C2 + col];
    g_h2[(size_t)m*C2 + col] = acc;
}

// ---------------- fused relation head (per pair): LN + relu + dot ----------------
__global__ void k_rel(const int* __restrict__ pidx,
                      const float* __restrict__ relb1, const float* __restrict__ lng,
                      const float* __restrict__ lnb, const float* __restrict__ relW2,
                      const float* __restrict__ relb2, float* __restrict__ out){
    __shared__ float sb1[256], sg[256], sbb[256], sw2[256];
    int r = blockIdx.y;
    int tid = threadIdx.x;
    sb1[tid] = relb1[r*256+tid];
    sg[tid]  = lng[r*256+tid];
    sbb[tid] = lnb[r*256+tid];
    sw2[tid] = relW2[r*256+tid];
    __syncthreads();

    int w = tid >> 5, lane = tid & 31;
    int p = blockIdx.x*8 + w;
    int i = pidx[p*2], j = pidx[p*2+1];
    const float* ti = g_tb + ((size_t)(r*2+0)*Ndim + i)*RHID;
    const float* tj = g_tb + ((size_t)(r*2+1)*Ndim + j)*RHID;

    float v[8]; float s1 = 0.f, s2 = 0.f;
    #pragma unroll
    for(int t=0;t<8;t++){
        int k = lane + 32*t;
        float x = ti[k] + tj[k] + sb1[k];
        v[t] = x; s1 += x; s2 += x*x;
    }
    s1 = warpSum(s1); s2 = warpSum(s2);
    float mu  = s1 * (1.0f/256.0f);
    float var = s2 * (1.0f/256.0f) - mu*mu;
    float rinv = rsqrtf(var + LNEPS);

    float acc = 0.f;
    #pragma unroll
    for(int t=0;t<8;t++){
        int k = lane + 32*t;
        float x = (v[t]-mu)*rinv*sg[k] + sbb[k];
        x = fmaxf(x, 0.f);
        acc += x * sw2[k];
    }
    acc = warpSum(acc);
    if(lane==0) out[(size_t)r*Pdim + p] = acc + relb2[r];
}

// ---------------- launch ----------------
extern "C" void kernel_launch(void* const* d_in, const int* in_sizes, int n_in,
                              void* d_out, int out_size){
    const float* seq     = (const float*)d_in[0];
    const int*   est     = (const int*)  d_in[1];
    const int*   elen    = (const int*)  d_in[2];
    const int*   ebat    = (const int*)  d_in[3];
    const int*   ei      = (const int*)  d_in[4];
    const int*   pidx    = (const int*)  d_in[5];
    const float* W1      = (const float*)d_in[6];
    const float* a_src1  = (const float*)d_in[7];
    const float* a_dst1  = (const float*)d_in[8];
    const float* b1      = (const float*)d_in[9];
    const float* W2      = (const float*)d_in[10];
    const float* a_src2  = (const float*)d_in[11];
    const float* a_dst2  = (const float*)d_in[12];
    const float* b2      = (const float*)d_in[13];
    const float* relW1   = (const float*)d_in[14];
    const float* relb1   = (const float*)d_in[15];
    const float* ln_g    = (const float*)d_in[16];
    const float* ln_b    = (const float*)d_in[17];
    const float* relW2   = (const float*)d_in[18];
    const float* relb2   = (const float*)d_in[19];
    const float* nerW1   = (const float*)d_in[20];
    const float* nerb1   = (const float*)d_in[21];
    const float* nerW2   = (const float*)d_in[22];
    const float* nerb2   = (const float*)d_in[23];
    float* out = (float*)d_out;

    float* g_x0_p;   cudaGetSymbolAddress((void**)&g_x0_p,   g_x0);
    float* g_h1_p;   cudaGetSymbolAddress((void**)&g_h1_p,   g_h1);
    float* g_out1_p; cudaGetSymbolAddress((void**)&g_out1_p, g_out1);
    float* g_h2_p;   cudaGetSymbolAddress((void**)&g_h2_p,   g_h2);
    float* g_x2_p;   cudaGetSymbolAddress((void**)&g_x2_p,   g_x2);
    float* g_es1_p;  cudaGetSymbolAddress((void**)&g_es1_p,  g_es1);
    float* g_ed1_p;  cudaGetSymbolAddress((void**)&g_ed1_p,  g_ed1);
    float* g_es2_p;  cudaGetSymbolAddress((void**)&g_es2_p,  g_es2);
    float* g_ed2_p;  cudaGetSymbolAddress((void**)&g_ed2_p,  g_ed2);
    float* g_tb_p;   cudaGetSymbolAddress((void**)&g_tb_p,   g_tb);
    float* g_nh_p;   cudaGetSymbolAddress((void**)&g_nh_p,   g_nerhid);

    // NER head: hid = relu(seq @ nerW1 + b1)  [16384x768x256]
    k_gemm128<true,true><<<dim3(NERH/128, NERROWS/128, 1), 256>>>(
        seq, Hdim, nerW1, NERH, 0, nerb1, g_nh_p, NERH, 0, Hdim);
    k_ner2<<<NERROWS/8, 256>>>(g_nh_p, nerW2, nerb2, out);

    // entity pooling
    k_span_pool<<<Ndim, 192>>>(seq, est, elen, ebat);

    // GAT layer 1 linear: h1 = x0 @ W1  (4096x768x512)
    k_gemm128<false,false><<<dim3(F1/128, Ndim/128, 1), 256>>>(
        g_x0_p, Hdim, W1, F1, 0, nullptr, g_h1_p, F1, 0, Hdim);

    // CSR build (shared by both layers)
    k_csr_init<<<(Ndim+255)/256, 256>>>();
    k_csr_count<<<(ETOT+255)/256, 256>>>(ei);
    k_csr_scan<<<1, 1024>>>();
    k_csr_scatter<<<(ETOT+255)/256, 256>>>(ei);

    // GAT layer 1 attention + aggregation (+bias, relu)
    k_attn_coef<H1, C1><<<Ndim, 128>>>(g_h1_p, a_src1, a_dst1, g_es1_p, g_ed1_p);
    k_gat_agg<H1, C1, true><<<Ndim, 128>>>(g_h1_p, g_es1_p, g_ed1_p, b1, g_out1_p);

    // GAT layer 2
    k_gemm2<<<Ndim, 64>>>(g_out1_p, W2);
    k_attn_coef<1, C2><<<Ndim, 32>>>(g_h2_p, a_src2, a_dst2, g_es2_p, g_ed2_p);
    k_gat_agg<1, C2, false><<<Ndim, 32>>>(g_h2_p, g_es2_p, g_ed2_p, b2, g_x2_p);

    // per-node relation contributions: tb[z] = x2 @ relW1[z*64:(z+1)*64]  (z = r*2 + half)
    k_gemm128<false,false><<<dim3(RHID/128, Ndim/128, 12), 256>>>(
        g_x2_p, C2, relW1, RHID, (long)64*RHID, nullptr,
        g_tb_p, RHID, (long)Ndim*RHID, C2);

    // fused relation classifier per pair
    k_rel<<<dim3(Pdim/8, NREL), 256>>>(pidx, relb1, ln_g, ln_b, relW2, relb2, out + NER_OUT_ELEMS);
}

// round 4
// speedup vs baseline: 1.6839x; 1.4856x over previous
#include <cuda_runtime.h>
#include <cuda_bf16.h>
#include <math.h>
#include <stdint.h>

// ---------------- problem constants ----------------
#define Bdim 32
#define Sdim 512
#define Hdim 768
#define Ndim 4096
#define Edim 131072
#define Pdim 65536
#define ETOT (Edim + Ndim)       // 135168 (self loops appended)
#define H1 4
#define C1 128
#define F1 (H1*C1)               // 512
#define C2 64
#define NREL 6
#define RHID 256
#define NERH 256
#define NERL 9
#define SLOPE 0.2f
#define LNEPS 1e-5f
#define NER_OUT_ELEMS (Bdim*Sdim*NERL)   // 147456
#define NERROWS (Bdim*Sdim)              // 16384

// ---------------- device scratch ----------------
__device__ float g_x0[Ndim*Hdim];
__device__ float g_h1[Ndim*F1];
__device__ float g_out1[Ndim*F1];
__device__ float g_h2[Ndim*C2];
__device__ float g_x2[Ndim*C2];
__device__ float g_es1[Ndim*H1], g_ed1[Ndim*H1];
__device__ float g_es2[Ndim],    g_ed2[Ndim];
__device__ int   g_deg[Ndim], g_cursor[Ndim], g_rowstart[Ndim+1];
__device__ int   g_csr[ETOT];
__device__ float g_tb[12*Ndim*RHID];
__device__ float g_nerhid[NERROWS*NERH];
// split bf16 planes (hi/lo) for activations and weights
__device__ __nv_bfloat16 g_sqh[NERROWS*Hdim], g_sql[NERROWS*Hdim];
__device__ __nv_bfloat16 g_x0h[Ndim*Hdim],    g_x0l[Ndim*Hdim];
__device__ __nv_bfloat16 g_x2h[Ndim*C2],      g_x2l[Ndim*C2];
__device__ __nv_bfloat16 g_w1h[Hdim*F1],      g_w1l[Hdim*F1];
__device__ __nv_bfloat16 g_wnh[Hdim*NERH],    g_wnl[Hdim*NERH];
__device__ __nv_bfloat16 g_wrh[12*C2*RHID],   g_wrl[12*C2*RHID];

// ---------------- helpers ----------------
__device__ __forceinline__ float warpSum(float v){
    #pragma unroll
    for(int o=16;o;o>>=1) v += __shfl_xor_sync(0xffffffffu, v, o);
    return v;
}
__device__ __forceinline__ float warpMax(float v){
    #pragma unroll
    for(int o=16;o;o>>=1) v = fmaxf(v, __shfl_xor_sync(0xffffffffu, v, o));
    return v;
}
__device__ __forceinline__ uint32_t smem_u32(const void* p){
    uint32_t a;
    asm("{ .reg .u64 t; cvta.to.shared.u64 t, %1; cvt.u32.u64 %0, t; }" : "=r"(a) : "l"(p));
    return a;
}
__device__ __forceinline__ unsigned pack_bf2(__nv_bfloat16 a, __nv_bfloat16 b){
    __nv_bfloat162 t; t.x = a; t.y = b;
    return *reinterpret_cast<unsigned*>(&t);
}
__device__ __forceinline__ void cp16(uint32_t dst, const void* src){
    asm volatile("cp.async.ca.shared.global [%0], [%1], 16;" :: "r"(dst), "l"(src) : "memory");
}
__device__ __forceinline__ void ldsm4(uint32_t* r, uint32_t addr){
    asm volatile("ldmatrix.sync.aligned.m8n8.x4.shared.b16 {%0,%1,%2,%3}, [%4];"
        : "=r"(r[0]), "=r"(r[1]), "=r"(r[2]), "=r"(r[3]) : "r"(addr));
}
__device__ __forceinline__ void ldsm4t(uint32_t* r, uint32_t addr){
    asm volatile("ldmatrix.sync.aligned.m8n8.x4.trans.shared.b16 {%0,%1,%2,%3}, [%4];"
        : "=r"(r[0]), "=r"(r[1]), "=r"(r[2]), "=r"(r[3]) : "r"(addr));
}
__device__ __forceinline__ void mma16816(float* d, const uint32_t* a, uint32_t b0, uint32_t b1){
    asm volatile(
        "mma.sync.aligned.m16n8k16.row.col.f32.bf16.bf16.f32 "
        "{%0,%1,%2,%3}, {%4,%5,%6,%7}, {%8,%9}, {%0,%1,%2,%3};"
        : "+f"(d[0]), "+f"(d[1]), "+f"(d[2]), "+f"(d[3])
        : "r"(a[0]), "r"(a[1]), "r"(a[2]), "r"(a[3]), "r"(b0), "r"(b1));
}

// ---------------- split fp32 -> bf16 hi/lo planes (elementwise) ----------------
__global__ void k_split(const float4* __restrict__ in, uint2* __restrict__ hi,
                        uint2* __restrict__ lo, int n4){
    int i = blockIdx.x*blockDim.x + threadIdx.x;
    if(i >= n4) return;
    float4 v = in[i];
    __nv_bfloat16 h0=__float2bfloat16(v.x), h1=__float2bfloat16(v.y);
    __nv_bfloat16 h2=__float2bfloat16(v.z), h3=__float2bfloat16(v.w);
    __nv_bfloat16 l0=__float2bfloat16(v.x-__bfloat162float(h0));
    __nv_bfloat16 l1=__float2bfloat16(v.y-__bfloat162float(h1));
    __nv_bfloat16 l2=__float2bfloat16(v.z-__bfloat162float(h2));
    __nv_bfloat16 l3=__float2bfloat16(v.w-__bfloat162float(h3));
    hi[i] = make_uint2(pack_bf2(h0,h1), pack_bf2(h2,h3));
    lo[i] = make_uint2(pack_bf2(l0,l1), pack_bf2(l2,l3));
}

// ---------------- split-bf16 HMMA GEMM ----------------
// C[m,n] = sum_k act[m,k]*W[k,n] (+bias[n]) (relu?)
// grid (N/128, M/128, Z), block 256 (8 warps, warp tile 64x32), K % 32 == 0
#define SA 40
#define SB 136
#define A_PL (128*SA*2)            // 10240
#define B_PL (32*SB*2)             // 8704
#define BOFF (2*A_PL)              // 20480
#define STAGE_SZ (BOFF + 2*B_PL)   // 37888
#define HMMA_SMEM (2*STAGE_SZ)     // 75776
__global__ void __launch_bounds__(256) k_hmma(
        const __nv_bfloat16* __restrict__ aHi, const __nv_bfloat16* __restrict__ aLo, int K,
        const __nv_bfloat16* __restrict__ wHi, const __nv_bfloat16* __restrict__ wLo, int N,
        long wStrideZ, const float* __restrict__ bias, int reluFlag,
        float* __restrict__ C, int ldc, long cStrideZ){
    extern __shared__ char sm_buf[];
    int tid = threadIdx.x, lane = tid & 31, warp = tid >> 5;
    int wm = warp & 1, wn = warp >> 1;
    int grp = lane >> 3, rr = lane & 7;
    int arow = rr + (grp & 1)*8;       // row (or k) within 16
    int acol = (grp >> 1)*8;           // col offset within 16

    int n0 = blockIdx.x*128, m0 = blockIdx.y*128, z = blockIdx.z;
    const __nv_bfloat16* wzh = wHi + (size_t)z*wStrideZ;
    const __nv_bfloat16* wzl = wLo + (size_t)z*wStrideZ;
    int nc = K >> 5;

    float acc[4][4][4];
    #pragma unroll
    for(int a=0;a<4;a++)
        #pragma unroll
        for(int b=0;b<4;b++)
            #pragma unroll
            for(int c=0;c<4;c++) acc[a][b][c] = 0.f;

    uint32_t sb0 = smem_u32(sm_buf);

    // ---- async load of chunk kc into stage st ----
    #define ISSUE(kc, st) do{                                                        \
        uint32_t sb = sb0 + (st)*STAGE_SZ;                                           \
        _Pragma("unroll")                                                            \
        for(int i=0;i<2;i++){                                                        \
            int idx = tid + i*256; int row = idx >> 2, k8 = idx & 3;                 \
            size_t go = (size_t)(m0+row)*K + (kc)*32 + k8*8;                         \
            uint32_t d = sb + row*80 + k8*16;                                        \
            cp16(d,        aHi + go);                                                \
            cp16(d + A_PL, aLo + go);                                                \
        }                                                                            \
        _Pragma("unroll")                                                            \
        for(int i=0;i<2;i++){                                                        \
            int idx = tid + i*256; int kr = idx >> 4, ncol = idx & 15;               \
            size_t go = (size_t)((kc)*32 + kr)*N + n0 + ncol*8;                      \
            uint32_t d = sb + BOFF + kr*272 + ncol*16;                               \
            cp16(d,        wzh + go);                                                \
            cp16(d + B_PL, wzl + go);                                                \
        }                                                                            \
        asm volatile("cp.async.commit_group;" ::: "memory");                         \
    }while(0)

    ISSUE(0, 0);
    for(int kc=0; kc<nc; kc++){
        if(kc+1 < nc){
            ISSUE(kc+1, (kc+1)&1);
            asm volatile("cp.async.wait_group 1;" ::: "memory");
        }else{
            asm volatile("cp.async.wait_group 0;" ::: "memory");
        }
        __syncthreads();
        uint32_t sb = sb0 + (kc&1)*STAGE_SZ;
        uint32_t aBase = sb + ((wm*64 + arow)*SA + acol)*2;
        uint32_t bBase = sb + BOFF + (arow*SB + wn*32 + acol)*2;
        #pragma unroll
        for(int kk=0; kk<2; kk++){
            uint32_t af[4][2][4];
            #pragma unroll
            for(int mt=0; mt<4; mt++){
                uint32_t ad = aBase + mt*(16*SA*2) + kk*32;
                ldsm4(af[mt][0], ad);
                ldsm4(af[mt][1], ad + A_PL);
            }
            uint32_t bfr[2][2][4];
            #pragma unroll
            for(int pr=0; pr<2; pr++){
                uint32_t bd = bBase + kk*(16*SB*2) + pr*32;
                ldsm4t(bfr[pr][0], bd);
                ldsm4t(bfr[pr][1], bd + B_PL);
            }
            #pragma unroll
            for(int mt=0; mt<4; mt++)
                #pragma unroll
                for(int nt=0; nt<4; nt++){
                    int pr = nt >> 1, hf = (nt & 1)*2;
                    uint32_t bh0 = bfr[pr][0][hf], bh1 = bfr[pr][0][hf+1];
                    uint32_t bl0 = bfr[pr][1][hf], bl1 = bfr[pr][1][hf+1];
                    mma16816(acc[mt][nt], af[mt][0], bh0, bh1);   // ah*bh
                    mma16816(acc[mt][nt], af[mt][0], bl0, bl1);   // ah*bl
                    mma16816(acc[mt][nt], af[mt][1], bh0, bh1);   // al*bh
                }
        }
        __syncthreads();
    }
    #undef ISSUE

    // epilogue
    float* Cz = C + (size_t)z*cStrideZ;
    #pragma unroll
    for(int mt=0; mt<4; mt++){
        int m = m0 + wm*64 + mt*16 + (lane >> 2);
        #pragma unroll
        for(int nt=0; nt<4; nt++){
            int n = n0 + wn*32 + nt*8 + (lane & 3)*2;
            float b0v = 0.f, b1v = 0.f;
            if(bias){ b0v = bias[n]; b1v = bias[n+1]; }
            float v0 = acc[mt][nt][0] + b0v, v1 = acc[mt][nt][1] + b1v;
            float v2 = acc[mt][nt][2] + b0v, v3 = acc[mt][nt][3] + b1v;
            if(reluFlag){ v0=fmaxf(v0,0.f); v1=fmaxf(v1,0.f); v2=fmaxf(v2,0.f); v3=fmaxf(v3,0.f); }
            *reinterpret_cast<float2*>(Cz + (size_t)m*ldc + n)     = make_float2(v0, v1);
            *reinterpret_cast<float2*>(Cz + (size_t)(m+8)*ldc + n) = make_float2(v2, v3);
        }
    }
}

// ---------------- 1) entity span mean pooling ----------------
__global__ void k_span_pool(const float* __restrict__ seq,
                            const int* __restrict__ est, const int* __restrict__ elen,
                            const int* __restrict__ ebat){
    int n = blockIdx.x;
    int b = ebat[n], st = est[n], len = elen[n];
    const float* base = seq + ((size_t)b*Sdim + st)*Hdim + threadIdx.x*4;
    float4 acc = make_float4(0.f,0.f,0.f,0.f);
    for(int r=0; r<=len; r++){
        float4 t = *reinterpret_cast<const float4*>(base + (size_t)r*Hdim);
        acc.x += t.x; acc.y += t.y; acc.z += t.z; acc.w += t.w;
    }
    float inv = 1.0f/(float)(len+1);
    acc.x*=inv; acc.y*=inv; acc.z*=inv; acc.w*=inv;
    *reinterpret_cast<float4*>(&g_x0[(size_t)n*Hdim + threadIdx.x*4]) = acc;
}

// ---------------- NER stage 2 ----------------
__global__ void k_ner2(const float* __restrict__ hid, const float* __restrict__ W2s,
                       const float* __restrict__ b2, float* __restrict__ out){
    __shared__ float sW2[NERH*NERL];
    int tid = threadIdx.x;
    for(int j=tid; j<NERH*NERL; j+=256) sW2[j] = W2s[j];
    __syncthreads();
    int w = tid >> 5, lane = tid & 31;
    int row = blockIdx.x*8 + w;
    const float* hp = hid + (size_t)row*NERH;
    float o[NERL];
    #pragma unroll
    for(int c=0;c<NERL;c++) o[c]=0.f;
    #pragma unroll
    for(int t=0;t<8;t++){
        int k = lane + 32*t;
        float hv = hp[k];
        #pragma unroll
        for(int c=0;c<NERL;c++) o[c] += hv * sW2[k*NERL + c];
    }
    #pragma unroll
    for(int c=0;c<NERL;c++){
        float s = warpSum(o[c]);
        if(lane==0) out[(size_t)row*NERL + c] = s + b2[c];
    }
}

// ---------------- GAT attention coefficients ----------------
template<int HEADS,int C>
__global__ void k_attn_coef(const float* __restrict__ h,
                            const float* __restrict__ a_src, const float* __restrict__ a_dst,
                            float* __restrict__ es, float* __restrict__ ed){
    const int F = HEADS*C;
    int n = blockIdx.x;
    int hh = threadIdx.x >> 5, lane = threadIdx.x & 31;
    float s1 = 0.f, s2 = 0.f;
    #pragma unroll
    for(int i=0;i<C/32;i++){
        float v = h[(size_t)n*F + hh*C + lane + 32*i];
        s1 += v * a_src[hh*C + lane + 32*i];
        s2 += v * a_dst[hh*C + lane + 32*i];
    }
    s1 = warpSum(s1); s2 = warpSum(s2);
    if(lane==0){ es[n*HEADS+hh] = s1; ed[n*HEADS+hh] = s2; }
}

// ---------------- CSR build ----------------
__global__ void k_csr_init(){
    int i = blockIdx.x*blockDim.x + threadIdx.x;
    if(i < Ndim){ g_deg[i]=0; g_cursor[i]=0; }
}
__global__ void k_csr_count(const int* __restrict__ ei){
    int e = blockIdx.x*blockDim.x + threadIdx.x;
    if(e >= ETOT) return;
    int dst = (e < Edim) ? ei[Edim + e] : (e - Edim);
    atomicAdd(&g_deg[dst], 1);
}
__global__ void k_csr_scan(){
    __shared__ int s[1024];
    int t = threadIdx.x;
    int v0 = g_deg[t*4+0], v1 = g_deg[t*4+1], v2 = g_deg[t*4+2], v3 = g_deg[t*4+3];
    int c0 = v0, c1 = c0+v1, c2 = c1+v2, c3 = c2+v3;
    s[t] = c3;
    __syncthreads();
    for(int off=1; off<1024; off<<=1){
        int x = (t >= off) ? s[t-off] : 0;
        __syncthreads();
        s[t] += x;
        __syncthreads();
    }
    int excl = s[t] - c3;
    g_rowstart[t*4+1] = excl + c0;
    g_rowstart[t*4+2] = excl + c1;
    g_rowstart[t*4+3] = excl + c2;
    g_rowstart[t*4+4] = excl + c3;
    if(t==0) g_rowstart[0] = 0;
}
__global__ void k_csr_scatter(const int* __restrict__ ei){
    int e = blockIdx.x*blockDim.x + threadIdx.x;
    if(e >= ETOT) return;
    int src, dst;
    if(e < Edim){ src = ei[e]; dst = ei[Edim + e]; }
    else        { src = e - Edim; dst = src; }
    int pos = g_rowstart[dst] + atomicAdd(&g_cursor[dst], 1);
    g_csr[pos] = src;
}

// ---------------- GAT softmax + aggregation ----------------
template<int HEADS,int C,bool RELU>
__global__ void k_gat_agg(const float* __restrict__ h,
                          const float* __restrict__ es, const float* __restrict__ ed,
                          const float* __restrict__ bias, float* __restrict__ out){
    const int F = HEADS*C;
    int d = blockIdx.x;
    int hh = threadIdx.x >> 5, lane = threadIdx.x & 31;
    int rs = g_rowstart[d], re = g_rowstart[d+1];
    float edv = ed[d*HEADS + hh];

    float m = -1e30f;
    for(int e=rs+lane; e<re; e+=32){
        int s = g_csr[e];
        float t = es[s*HEADS+hh] + edv;
        t = (t > 0.f) ? t : SLOPE*t;
        m = fmaxf(m, t);
    }
    m = warpMax(m);

    float den = 0.f;
    for(int e=rs+lane; e<re; e+=32){
        int s = g_csr[e];
        float t = es[s*HEADS+hh] + edv;
        t = (t > 0.f) ? t : SLOPE*t;
        den += __expf(t - m);
    }
    den = warpSum(den);
    float inv = 1.0f/den;

    float acc[C/32];
    #pragma unroll
    for(int i=0;i<C/32;i++) acc[i]=0.f;

    for(int e=rs; e<re; e++){
        int s = g_csr[e];
        float t = es[s*HEADS+hh] + edv;
        t = (t > 0.f) ? t : SLOPE*t;
        float w = __expf(t - m)*inv;
        const float* hp = h + (size_t)s*F + hh*C + lane;
        #pragma unroll
        for(int i=0;i<C/32;i++) acc[i] += w*hp[32*i];
    }
    #pragma unroll
    for(int i=0;i<C/32;i++){
        float v = acc[i] + bias[hh*C + lane + 32*i];
        if(RELU) v = fmaxf(v, 0.f);
        out[(size_t)d*F + hh*C + lane + 32*i] = v;
    }
}

// ---------------- layer2 linear: h2 = out1 @ W2 ----------------
__global__ void k_gemm2(const float* __restrict__ A, const float* __restrict__ W){
    __shared__ float sA[F1];
    int m = blockIdx.x;
    for(int k=threadIdx.x; k<F1; k+=64) sA[k] = A[(size_t)m*F1 + k];
    __syncthreads();
    int col = threadIdx.x;
    float acc = 0.f;
    #pragma unroll 8
    for(int k=0;k<F1;k++) acc += sA[k]*W[(size_t)k*C2 + col];
    g_h2[(size_t)m*C2 + col] = acc;
}

// ---------------- fused relation head ----------------
__global__ void k_rel(const int* __restrict__ pidx,
                      const float* __restrict__ relb1, const float* __restrict__ lng,
                      const float* __restrict__ lnb, const float* __restrict__ relW2,
                      const float* __restrict__ relb2, float* __restrict__ out){
    __shared__ float sb1[256], sg[256], sbb[256], sw2[256];
    int r = blockIdx.y;
    int tid = threadIdx.x;
    sb1[tid] = relb1[r*256+tid];
    sg[tid]  = lng[r*256+tid];
    sbb[tid] = lnb[r*256+tid];
    sw2[tid] = relW2[r*256+tid];
    __syncthreads();

    int w = tid >> 5, lane = tid & 31;
    int p = blockIdx.x*8 + w;
    int i = pidx[p*2], j = pidx[p*2+1];
    const float* ti = g_tb + ((size_t)(r*2+0)*Ndim + i)*RHID;
    const float* tj = g_tb + ((size_t)(r*2+1)*Ndim + j)*RHID;

    float v[8]; float s1 = 0.f, s2 = 0.f;
    #pragma unroll
    for(int t=0;t<8;t++){
        int k = lane + 32*t;
        float x = ti[k] + tj[k] + sb1[k];
        v[t] = x; s1 += x; s2 += x*x;
    }
    s1 = warpSum(s1); s2 = warpSum(s2);
    float mu  = s1 * (1.0f/256.0f);
    float var = s2 * (1.0f/256.0f) - mu*mu;
    float rinv = rsqrtf(var + LNEPS);

    float acc = 0.f;
    #pragma unroll
    for(int t=0;t<8;t++){
        int k = lane + 32*t;
        float x = (v[t]-mu)*rinv*sg[k] + sbb[k];
        x = fmaxf(x, 0.f);
        acc += x * sw2[k];
    }
    acc = warpSum(acc);
    if(lane==0) out[(size_t)r*Pdim + p] = acc + relb2[r];
}

// ---------------- launch ----------------
extern "C" void kernel_launch(void* const* d_in, const int* in_sizes, int n_in,
                              void* d_out, int out_size){
    const float* seq     = (const float*)d_in[0];
    const int*   est     = (const int*)  d_in[1];
    const int*   elen    = (const int*)  d_in[2];
    const int*   ebat    = (const int*)  d_in[3];
    const int*   ei      = (const int*)  d_in[4];
    const int*   pidx    = (const int*)  d_in[5];
    const float* W1      = (const float*)d_in[6];
    const float* a_src1  = (const float*)d_in[7];
    const float* a_dst1  = (const float*)d_in[8];
    const float* b1      = (const float*)d_in[9];
    const float* W2      = (const float*)d_in[10];
    const float* a_src2  = (const float*)d_in[11];
    const float* a_dst2  = (const float*)d_in[12];
    const float* b2      = (const float*)d_in[13];
    const float* relW1   = (const float*)d_in[14];
    const float* relb1   = (const float*)d_in[15];
    const float* ln_g    = (const float*)d_in[16];
    const float* ln_b    = (const float*)d_in[17];
    const float* relW2   = (const float*)d_in[18];
    const float* relb2   = (const float*)d_in[19];
    const float* nerW1   = (const float*)d_in[20];
    const float* nerb1   = (const float*)d_in[21];
    const float* nerW2   = (const float*)d_in[22];
    const float* nerb2   = (const float*)d_in[23];
    float* out = (float*)d_out;

    float* g_x0_p;   cudaGetSymbolAddress((void**)&g_x0_p,   g_x0);
    float* g_h1_p;   cudaGetSymbolAddress((void**)&g_h1_p,   g_h1);
    float* g_out1_p; cudaGetSymbolAddress((void**)&g_out1_p, g_out1);
    float* g_h2_p;   cudaGetSymbolAddress((void**)&g_h2_p,   g_h2);
    float* g_x2_p;   cudaGetSymbolAddress((void**)&g_x2_p,   g_x2);
    float* g_es1_p;  cudaGetSymbolAddress((void**)&g_es1_p,  g_es1);
    float* g_ed1_p;  cudaGetSymbolAddress((void**)&g_ed1_p,  g_ed1);
    float* g_es2_p;  cudaGetSymbolAddress((void**)&g_es2_p,  g_es2);
    float* g_ed2_p;  cudaGetSymbolAddress((void**)&g_ed2_p,  g_ed2);
    float* g_tb_p;   cudaGetSymbolAddress((void**)&g_tb_p,   g_tb);
    float* g_nh_p;   cudaGetSymbolAddress((void**)&g_nh_p,   g_nerhid);
    __nv_bfloat16 *sqh,*sql,*x0h,*x0l,*x2h,*x2l,*w1h,*w1l,*wnh,*wnl,*wrh,*wrl;
    cudaGetSymbolAddress((void**)&sqh, g_sqh); cudaGetSymbolAddress((void**)&sql, g_sql);
    cudaGetSymbolAddress((void**)&x0h, g_x0h); cudaGetSymbolAddress((void**)&x0l, g_x0l);
    cudaGetSymbolAddress((void**)&x2h, g_x2h); cudaGetSymbolAddress((void**)&x2l, g_x2l);
    cudaGetSymbolAddress((void**)&w1h, g_w1h); cudaGetSymbolAddress((void**)&w1l, g_w1l);
    cudaGetSymbolAddress((void**)&wnh, g_wnh); cudaGetSymbolAddress((void**)&wnl, g_wnl);
    cudaGetSymbolAddress((void**)&wrh, g_wrh); cudaGetSymbolAddress((void**)&wrl, g_wrl);

    cudaFuncSetAttribute(k_hmma, cudaFuncAttributeMaxDynamicSharedMemorySize, HMMA_SMEM);

    // ---- split fp32 -> bf16 hi/lo planes ----
    #define SPLIT(src, dh, dl, cnt) \
        k_split<<<((cnt)/4 + 255)/256, 256>>>((const float4*)(src), (uint2*)(dh), (uint2*)(dl), (cnt)/4)
    SPLIT(seq,   sqh, sql, NERROWS*Hdim);
    SPLIT(W1,    w1h, w1l, Hdim*F1);
    SPLIT(nerW1, wnh, wnl, Hdim*NERH);
    SPLIT(relW1, wrh, wrl, 12*C2*RHID);

    // NER head stage1: hid = relu(seq @ nerW1 + b1)
    k_hmma<<<dim3(NERH/128, NERROWS/128, 1), 256, HMMA_SMEM>>>(
        sqh, sql, Hdim, wnh, wnl, NERH, 0, nerb1, 1, g_nh_p, NERH, 0);
    k_ner2<<<NERROWS/8, 256>>>(g_nh_p, nerW2, nerb2, out);

    // entity pooling + split
    k_span_pool<<<Ndim, 192>>>(seq, est, elen, ebat);
    SPLIT(g_x0_p, x0h, x0l, Ndim*Hdim);

    // GAT layer 1 linear: h1 = x0 @ W1
    k_hmma<<<dim3(F1/128, Ndim/128, 1), 256, HMMA_SMEM>>>(
        x0h, x0l, Hdim, w1h, w1l, F1, 0, nullptr, 0, g_h1_p, F1, 0);

    // CSR build
    k_csr_init<<<(Ndim+255)/256, 256>>>();
    k_csr_count<<<(ETOT+255)/256, 256>>>(ei);
    k_csr_scan<<<1, 1024>>>();
    k_csr_scatter<<<(ETOT+255)/256, 256>>>(ei);

    // GAT layer 1 attention + aggregation
    k_attn_coef<H1, C1><<<Ndim, 128>>>(g_h1_p, a_src1, a_dst1, g_es1_p, g_ed1_p);
    k_gat_agg<H1, C1, true><<<Ndim, 128>>>(g_h1_p, g_es1_p, g_ed1_p, b1, g_out1_p);

    // GAT layer 2
    k_gemm2<<<Ndim, 64>>>(g_out1_p, W2);
    k_attn_coef<1, C2><<<Ndim, 32>>>(g_h2_p, a_src2, a_dst2, g_es2_p, g_ed2_p);
    k_gat_agg<1, C2, false><<<Ndim, 32>>>(g_h2_p, g_es2_p, g_ed2_p, b2, g_x2_p);

    // per-node relation contributions: tb[z] = x2 @ relW1[z]  (z = r*2 + half), K=64
    SPLIT(g_x2_p, x2h, x2l, Ndim*C2);
    k_hmma<<<dim3(RHID/128, Ndim/128, 12), 256, HMMA_SMEM>>>(
        x2h, x2l, C2, wrh, wrl, RHID, (long)C2*RHID, nullptr, 0,
        g_tb_p, RHID, (long)Ndim*RHID);

    // fused relation classifier per pair
    k_rel<<<dim3(Pdim/8, NREL), 256>>>(pidx, relb1, ln_g, ln_b, relW2, relb2, out + NER_OUT_ELEMS);
    #undef SPLIT
}

// round 5
// speedup vs baseline: 1.9411x; 1.1528x over previous
#include <cuda_runtime.h>
#include <cuda_bf16.h>
#include <math.h>
#include <stdint.h>

// ---------------- problem constants ----------------
#define Bdim 32
#define Sdim 512
#define Hdim 768
#define Ndim 4096
#define Edim 131072
#define Pdim 65536
#define ETOT (Edim + Ndim)
#define H1 4
#define C1 128
#define F1 (H1*C1)               // 512
#define C2 64
#define NREL 6
#define RHID 256
#define NERH 256
#define NERL 9
#define SLOPE 0.2f
#define LNEPS 1e-5f
#define NER_OUT_ELEMS (Bdim*Sdim*NERL)
#define NERROWS (Bdim*Sdim)      // 16384

// ---------------- device scratch ----------------
__device__ float g_h1[Ndim*F1];          // GAT1 linear out (fp32)
__device__ float g_h2p[Ndim*128];        // GAT2 linear out, padded to 128 cols
__device__ float g_es1[Ndim*H1], g_ed1[Ndim*H1];
__device__ float g_es2[Ndim],    g_ed2[Ndim];
__device__ int   g_deg[Ndim], g_cursor[Ndim], g_rowstart[Ndim+1];
__device__ int   g_csr[ETOT];
__device__ int   g_pdeg[Ndim], g_pcur[Ndim], g_prow[Ndim+1];
__device__ int   g_psorted[Pdim];
__device__ float g_tb[12*Ndim*RHID];
__device__ float g_nerhid[NERROWS*NERH];
// split bf16 planes (hi/lo)
__device__ __nv_bfloat16 g_sqh[NERROWS*Hdim], g_sql[NERROWS*Hdim];
__device__ __nv_bfloat16 g_x0h[Ndim*Hdim],    g_x0l[Ndim*Hdim];
__device__ __nv_bfloat16 g_o1h[Ndim*F1],      g_o1l[Ndim*F1];
__device__ __nv_bfloat16 g_x2h[Ndim*C2],      g_x2l[Ndim*C2];
__device__ __nv_bfloat16 g_w1h[Hdim*F1],      g_w1l[Hdim*F1];
__device__ __nv_bfloat16 g_wnh[Hdim*NERH],    g_wnl[Hdim*NERH];
__device__ __nv_bfloat16 g_w2h[F1*128],       g_w2l[F1*128];
__device__ __nv_bfloat16 g_wrh[12*C2*RHID],   g_wrl[12*C2*RHID];

// ---------------- helpers ----------------
__device__ __forceinline__ float warpSum(float v){
    #pragma unroll
    for(int o=16;o;o>>=1) v += __shfl_xor_sync(0xffffffffu, v, o);
    return v;
}
__device__ __forceinline__ float warpMax(float v){
    #pragma unroll
    for(int o=16;o;o>>=1) v = fmaxf(v, __shfl_xor_sync(0xffffffffu, v, o));
    return v;
}
__device__ __forceinline__ uint32_t smem_u32(const void* p){
    uint32_t a;
    asm("{ .reg .u64 t; cvta.to.shared.u64 t, %1; cvt.u32.u64 %0, t; }" : "=r"(a) : "l"(p));
    return a;
}
__device__ __forceinline__ unsigned pack_bf2(__nv_bfloat16 a, __nv_bfloat16 b){
    __nv_bfloat162 t; t.x = a; t.y = b;
    return *reinterpret_cast<unsigned*>(&t);
}
__device__ __forceinline__ void cp16(uint32_t dst, const void* src){
    asm volatile("cp.async.ca.shared.global [%0], [%1], 16;" :: "r"(dst), "l"(src) : "memory");
}
__device__ __forceinline__ void ldsm4(uint32_t* r, uint32_t addr){
    asm volatile("ldmatrix.sync.aligned.m8n8.x4.shared.b16 {%0,%1,%2,%3}, [%4];"
        : "=r"(r[0]), "=r"(r[1]), "=r"(r[2]), "=r"(r[3]) : "r"(addr));
}
__device__ __forceinline__ void ldsm4t(uint32_t* r, uint32_t addr){
    asm volatile("ldmatrix.sync.aligned.m8n8.x4.trans.shared.b16 {%0,%1,%2,%3}, [%4];"
        : "=r"(r[0]), "=r"(r[1]), "=r"(r[2]), "=r"(r[3]) : "r"(addr));
}
__device__ __forceinline__ void mma16816(float* d, const uint32_t* a, uint32_t b0, uint32_t b1){
    asm volatile(
        "mma.sync.aligned.m16n8k16.row.col.f32.bf16.bf16.f32 "
        "{%0,%1,%2,%3}, {%4,%5,%6,%7}, {%8,%9}, {%0,%1,%2,%3};"
        : "+f"(d[0]), "+f"(d[1]), "+f"(d[2]), "+f"(d[3])
        : "r"(a[0]), "r"(a[1]), "r"(a[2]), "r"(a[3]), "r"(b0), "r"(b1));
}

// ---------------- split fp32 -> bf16 hi/lo planes ----------------
__global__ void k_split(const float4* __restrict__ in, uint2* __restrict__ hi,
                        uint2* __restrict__ lo, int n4){
    int i = blockIdx.x*blockDim.x + threadIdx.x;
    if(i >= n4) return;
    float4 v = in[i];
    __nv_bfloat16 h0=__float2bfloat16(v.x), h1=__float2bfloat16(v.y);
    __nv_bfloat16 h2=__float2bfloat16(v.z), h3=__float2bfloat16(v.w);
    __nv_bfloat16 l0=__float2bfloat16(v.x-__bfloat162float(h0));
    __nv_bfloat16 l1=__float2bfloat16(v.y-__bfloat162float(h1));
    __nv_bfloat16 l2=__float2bfloat16(v.z-__bfloat162float(h2));
    __nv_bfloat16 l3=__float2bfloat16(v.w-__bfloat162float(h3));
    hi[i] = make_uint2(pack_bf2(h0,h1), pack_bf2(h2,h3));
    lo[i] = make_uint2(pack_bf2(l0,l1), pack_bf2(l2,l3));
}

// split W2 [512,64] into padded [512,128] bf16 hi/lo (cols 64.. zero)
__global__ void k_split_padW2(const float* __restrict__ W2,
                              __nv_bfloat16* __restrict__ hi, __nv_bfloat16* __restrict__ lo){
    int idx = blockIdx.x*256 + threadIdx.x;   // 512*128
    int k = idx >> 7, c = idx & 127;
    float v = (c < C2) ? W2[k*C2 + c] : 0.f;
    __nv_bfloat16 h = __float2bfloat16(v);
    __nv_bfloat16 l = __float2bfloat16(v - __bfloat162float(h));
    hi[idx] = h; lo[idx] = l;
}

// ---------------- split-bf16 HMMA GEMM ----------------
#define SA 40
#define SB 136
#define A_PL (128*SA*2)
#define B_PL (32*SB*2)
#define BOFF (2*A_PL)
#define STAGE_SZ (BOFF + 2*B_PL)
#define HMMA_SMEM (2*STAGE_SZ)
__global__ void __launch_bounds__(256) k_hmma(
        const __nv_bfloat16* __restrict__ aHi, const __nv_bfloat16* __restrict__ aLo, int K,
        const __nv_bfloat16* __restrict__ wHi, const __nv_bfloat16* __restrict__ wLo, int N,
        long wStrideZ, const float* __restrict__ bias, int reluFlag,
        float* __restrict__ C, int ldc, long cStrideZ){
    extern __shared__ char sm_buf[];
    int tid = threadIdx.x, lane = tid & 31, warp = tid >> 5;
    int wm = warp & 1, wn = warp >> 1;
    int grp = lane >> 3, rr = lane & 7;
    int arow = rr + (grp & 1)*8;
    int acol = (grp >> 1)*8;

    int n0 = blockIdx.x*128, m0 = blockIdx.y*128, z = blockIdx.z;
    const __nv_bfloat16* wzh = wHi + (size_t)z*wStrideZ;
    const __nv_bfloat16* wzl = wLo + (size_t)z*wStrideZ;
    int nc = K >> 5;

    float acc[4][4][4];
    #pragma unroll
    for(int a=0;a<4;a++)
        #pragma unroll
        for(int b=0;b<4;b++)
            #pragma unroll
            for(int c=0;c<4;c++) acc[a][b][c] = 0.f;

    uint32_t sb0 = smem_u32(sm_buf);

    #define ISSUE(kc, st) do{                                                        \
        uint32_t sb = sb0 + (st)*STAGE_SZ;                                           \
        _Pragma("unroll")                                                            \
        for(int i=0;i<2;i++){                                                        \
            int idx = tid + i*256; int row = idx >> 2, k8 = idx & 3;                 \
            size_t go = (size_t)(m0+row)*K + (kc)*32 + k8*8;                         \
            uint32_t d = sb + row*80 + k8*16;                                        \
            cp16(d,        aHi + go);                                                \
            cp16(d + A_PL, aLo + go);                                                \
        }                                                                            \
        _Pragma("unroll")                                                            \
        for(int i=0;i<2;i++){                                                        \
            int idx = tid + i*256; int kr = idx >> 4, ncol = idx & 15;               \
            size_t go = (size_t)((kc)*32 + kr)*N + n0 + ncol*8;                      \
            uint32_t d = sb + BOFF + kr*272 + ncol*16;                               \
            cp16(d,        wzh + go);                                                \
            cp16(d + B_PL, wzl + go);                                                \
        }                                                                            \
        asm volatile("cp.async.commit_group;" ::: "memory");                         \
    }while(0)

    ISSUE(0, 0);
    for(int kc=0; kc<nc; kc++){
        if(kc+1 < nc){
            ISSUE(kc+1, (kc+1)&1);
            asm volatile("cp.async.wait_group 1;" ::: "memory");
        }else{
            asm volatile("cp.async.wait_group 0;" ::: "memory");
        }
        __syncthreads();
        uint32_t sb = sb0 + (kc&1)*STAGE_SZ;
        uint32_t aBase = sb + ((wm*64 + arow)*SA + acol)*2;
        uint32_t bBase = sb + BOFF + (arow*SB + wn*32 + acol)*2;
        #pragma unroll
        for(int kk=0; kk<2; kk++){
            uint32_t af[4][2][4];
            #pragma unroll
            for(int mt=0; mt<4; mt++){
                uint32_t ad = aBase + mt*(16*SA*2) + kk*32;
                ldsm4(af[mt][0], ad);
                ldsm4(af[mt][1], ad + A_PL);
            }
            uint32_t bfr[2][2][4];
            #pragma unroll
            for(int pr=0; pr<2; pr++){
                uint32_t bd = bBase + kk*(16*SB*2) + pr*32;
                ldsm4t(bfr[pr][0], bd);
                ldsm4t(bfr[pr][1], bd + B_PL);
            }
            #pragma unroll
            for(int mt=0; mt<4; mt++)
                #pragma unroll
                for(int nt=0; nt<4; nt++){
                    int pr = nt >> 1, hf = (nt & 1)*2;
                    uint32_t bh0 = bfr[pr][0][hf], bh1 = bfr[pr][0][hf+1];
                    uint32_t bl0 = bfr[pr][1][hf], bl1 = bfr[pr][1][hf+1];
                    mma16816(acc[mt][nt], af[mt][0], bh0, bh1);
                    mma16816(acc[mt][nt], af[mt][0], bl0, bl1);
                    mma16816(acc[mt][nt], af[mt][1], bh0, bh1);
                }
        }
        __syncthreads();
    }
    #undef ISSUE

    float* Cz = C + (size_t)z*cStrideZ;
    #pragma unroll
    for(int mt=0; mt<4; mt++){
        int m = m0 + wm*64 + mt*16 + (lane >> 2);
        #pragma unroll
        for(int nt=0; nt<4; nt++){
            int n = n0 + wn*32 + nt*8 + (lane & 3)*2;
            float b0v = 0.f, b1v = 0.f;
            if(bias){ b0v = bias[n]; b1v = bias[n+1]; }
            float v0 = acc[mt][nt][0] + b0v, v1 = acc[mt][nt][1] + b1v;
            float v2 = acc[mt][nt][2] + b0v, v3 = acc[mt][nt][3] + b1v;
            if(reluFlag){ v0=fmaxf(v0,0.f); v1=fmaxf(v1,0.f); v2=fmaxf(v2,0.f); v3=fmaxf(v3,0.f); }
            *reinterpret_cast<float2*>(Cz + (size_t)m*ldc + n)     = make_float2(v0, v1);
            *reinterpret_cast<float2*>(Cz + (size_t)(m+8)*ldc + n) = make_float2(v2, v3);
        }
    }
}

// ---------------- entity span mean pooling -> bf16 hi/lo planes ----------------
__global__ void k_span_pool(const float* __restrict__ seq,
                            const int* __restrict__ est, const int* __restrict__ elen,
                            const int* __restrict__ ebat,
                            __nv_bfloat16* __restrict__ xh, __nv_bfloat16* __restrict__ xl){
    int n = blockIdx.x;
    int b = ebat[n], st = est[n], len = elen[n];
    const float* base = seq + ((size_t)b*Sdim + st)*Hdim + threadIdx.x*4;
    float4 acc = make_float4(0.f,0.f,0.f,0.f);
    for(int r=0; r<=len; r++){
        float4 t = *reinterpret_cast<const float4*>(base + (size_t)r*Hdim);
        acc.x += t.x; acc.y += t.y; acc.z += t.z; acc.w += t.w;
    }
    float inv = 1.0f/(float)(len+1);
    acc.x*=inv; acc.y*=inv; acc.z*=inv; acc.w*=inv;
    __nv_bfloat16 h0=__float2bfloat16(acc.x), h1=__float2bfloat16(acc.y);
    __nv_bfloat16 h2=__float2bfloat16(acc.z), h3=__float2bfloat16(acc.w);
    __nv_bfloat16 l0=__float2bfloat16(acc.x-__bfloat162float(h0));
    __nv_bfloat16 l1=__float2bfloat16(acc.y-__bfloat162float(h1));
    __nv_bfloat16 l2=__float2bfloat16(acc.z-__bfloat162float(h2));
    __nv_bfloat16 l3=__float2bfloat16(acc.w-__bfloat162float(h3));
    size_t o = (size_t)n*Hdim + threadIdx.x*4;
    *reinterpret_cast<uint2*>(&xh[o]) = make_uint2(pack_bf2(h0,h1), pack_bf2(h2,h3));
    *reinterpret_cast<uint2*>(&xl[o]) = make_uint2(pack_bf2(l0,l1), pack_bf2(l2,l3));
}

// ---------------- NER stage 2 ----------------
__global__ void k_ner2(const float* __restrict__ hid, const float* __restrict__ W2s,
                       const float* __restrict__ b2, float* __restrict__ out){
    __shared__ float sW2[NERH*NERL];
    int tid = threadIdx.x;
    for(int j=tid; j<NERH*NERL; j+=256) sW2[j] = W2s[j];
    __syncthreads();
    int w = tid >> 5, lane = tid & 31;
    int row = blockIdx.x*8 + w;
    const float* hp = hid + (size_t)row*NERH;
    float o[NERL];
    #pragma unroll
    for(int c=0;c<NERL;c++) o[c]=0.f;
    #pragma unroll
    for(int t=0;t<8;t++){
        int k = lane + 32*t;
        float hv = hp[k];
        #pragma unroll
        for(int c=0;c<NERL;c++) o[c] += hv * sW2[k*NERL + c];
    }
    #pragma unroll
    for(int c=0;c<NERL;c++){
        float s = warpSum(o[c]);
        if(lane==0) out[(size_t)row*NERL + c] = s + b2[c];
    }
}

// ---------------- GAT attention coefficients ----------------
template<int HEADS,int C,int LD>
__global__ void k_attn_coef(const float* __restrict__ h,
                            const float* __restrict__ a_src, const float* __restrict__ a_dst,
                            float* __restrict__ es, float* __restrict__ ed){
    int n = blockIdx.x;
    int hh = threadIdx.x >> 5, lane = threadIdx.x & 31;
    float s1 = 0.f, s2 = 0.f;
    #pragma unroll
    for(int i=0;i<C/32;i++){
        float v = h[(size_t)n*LD + hh*C + lane + 32*i];
        s1 += v * a_src[hh*C + lane + 32*i];
        s2 += v * a_dst[hh*C + lane + 32*i];
    }
    s1 = warpSum(s1); s2 = warpSum(s2);
    if(lane==0){ es[n*HEADS+hh] = s1; ed[n*HEADS+hh] = s2; }
}

// ---------------- CSR + pair-sort build ----------------
__global__ void k_idx_init(){
    int i = blockIdx.x*blockDim.x + threadIdx.x;
    if(i < Ndim){ g_deg[i]=0; g_cursor[i]=0; g_pdeg[i]=0; g_pcur[i]=0; }
}
__global__ void k_csr_count(const int* __restrict__ ei){
    int e = blockIdx.x*blockDim.x + threadIdx.x;
    if(e >= ETOT) return;
    int dst = (e < Edim) ? ei[Edim + e] : (e - Edim);
    atomicAdd(&g_deg[dst], 1);
}
__global__ void k_pair_count(const int* __restrict__ pidx){
    int p = blockIdx.x*blockDim.x + threadIdx.x;
    if(p >= Pdim) return;
    atomicAdd(&g_pdeg[pidx[p*2]], 1);
}
__global__ void k_scan4096(const int* __restrict__ deg, int* __restrict__ rowstart){
    __shared__ int s[1024];
    int t = threadIdx.x;
    int v0 = deg[t*4+0], v1 = deg[t*4+1], v2 = deg[t*4+2], v3 = deg[t*4+3];
    int c0 = v0, c1 = c0+v1, c2 = c1+v2, c3 = c2+v3;
    s[t] = c3;
    __syncthreads();
    for(int off=1; off<1024; off<<=1){
        int x = (t >= off) ? s[t-off] : 0;
        __syncthreads();
        s[t] += x;
        __syncthreads();
    }
    int excl = s[t] - c3;
    rowstart[t*4+1] = excl + c0;
    rowstart[t*4+2] = excl + c1;
    rowstart[t*4+3] = excl + c2;
    rowstart[t*4+4] = excl + c3;
    if(t==0) rowstart[0] = 0;
}
__global__ void k_csr_scatter(const int* __restrict__ ei){
    int e = blockIdx.x*blockDim.x + threadIdx.x;
    if(e >= ETOT) return;
    int src, dst;
    if(e < Edim){ src = ei[e]; dst = ei[Edim + e]; }
    else        { src = e - Edim; dst = src; }
    int pos = g_rowstart[dst] + atomicAdd(&g_cursor[dst], 1);
    g_csr[pos] = src;
}
__global__ void k_pair_scatter(const int* __restrict__ pidx){
    int p = blockIdx.x*blockDim.x + threadIdx.x;
    if(p >= Pdim) return;
    int i = pidx[p*2];
    int pos = g_prow[i] + atomicAdd(&g_pcur[i], 1);
    g_psorted[pos] = p;
}

// ---------------- GAT softmax + aggregation ----------------
template<int HEADS,int C,int LD,bool RELU,bool SPLIT>
__global__ void k_gat_agg(const float* __restrict__ h,
                          const float* __restrict__ es, const float* __restrict__ ed,
                          const float* __restrict__ bias, float* __restrict__ out,
                          __nv_bfloat16* __restrict__ outH, __nv_bfloat16* __restrict__ outL){
    const int F = HEADS*C;
    int d = blockIdx.x;
    int hh = threadIdx.x >> 5, lane = threadIdx.x & 31;
    int rs = g_rowstart[d], re = g_rowstart[d+1];
    float edv = ed[d*HEADS + hh];

    float m = -1e30f;
    for(int e=rs+lane; e<re; e+=32){
        int s = g_csr[e];
        float t = es[s*HEADS+hh] + edv;
        t = (t > 0.f) ? t : SLOPE*t;
        m = fmaxf(m, t);
    }
    m = warpMax(m);

    float den = 0.f;
    for(int e=rs+lane; e<re; e+=32){
        int s = g_csr[e];
        float t = es[s*HEADS+hh] + edv;
        t = (t > 0.f) ? t : SLOPE*t;
        den += __expf(t - m);
    }
    den = warpSum(den);
    float inv = 1.0f/den;

    float acc[C/32];
    #pragma unroll
    for(int i=0;i<C/32;i++) acc[i]=0.f;

    for(int e=rs; e<re; e++){
        int s = g_csr[e];
        float t = es[s*HEADS+hh] + edv;
        t = (t > 0.f) ? t : SLOPE*t;
        float w = __expf(t - m)*inv;
        const float* hp = h + (size_t)s*LD + hh*C + lane;
        #pragma unroll
        for(int i=0;i<C/32;i++) acc[i] += w*hp[32*i];
    }
    #pragma unroll
    for(int i=0;i<C/32;i++){
        float v = acc[i] + bias[hh*C + lane + 32*i];
        if(RELU) v = fmaxf(v, 0.f);
        size_t o = (size_t)d*F + hh*C + lane + 32*i;
        if(SPLIT){
            __nv_bfloat16 hb = __float2bfloat16(v);
            outH[o] = hb;
            outL[o] = __float2bfloat16(v - __bfloat162float(hb));
        }else{
            out[o] = v;
        }
    }
}

// ---------------- fused relation head, grouped by left entity ----------------
__global__ void k_rel_g(const int* __restrict__ pidx,
                        const float* __restrict__ relb1, const float* __restrict__ lng,
                        const float* __restrict__ lnb, const float* __restrict__ relW2,
                        const float* __restrict__ relb2, float* __restrict__ out){
    __shared__ float sb1[256], sg[256], sbb[256], sw2[256], sti[256];
    int i = blockIdx.x, r = blockIdx.y;
    int rs = g_prow[i], re = g_prow[i+1];
    if(rs == re) return;
    int tid = threadIdx.x;
    sb1[tid] = relb1[r*256+tid];
    sg[tid]  = lng[r*256+tid];
    sbb[tid] = lnb[r*256+tid];
    sw2[tid] = relW2[r*256+tid];
    sti[tid] = g_tb[((size_t)(r*2)*Ndim + i)*RHID + tid];
    __syncthreads();

    int w = tid >> 5, lane = tid & 31;
    float rb2 = relb2[r];
    for(int idx = rs + w; idx < re; idx += 8){
        int p = g_psorted[idx];
        int j = pidx[p*2+1];
        const float* tj = g_tb + ((size_t)(r*2+1)*Ndim + j)*RHID;
        float v[8]; float s1 = 0.f, s2 = 0.f;
        #pragma unroll
        for(int t=0;t<8;t++){
            int k = lane + 32*t;
            float x = sti[k] + tj[k] + sb1[k];
            v[t] = x; s1 += x; s2 += x*x;
        }
        s1 = warpSum(s1); s2 = warpSum(s2);
        float mu  = s1 * (1.0f/256.0f);
        float var = s2 * (1.0f/256.0f) - mu*mu;
        float rinv = rsqrtf(var + LNEPS);
        float acc = 0.f;
        #pragma unroll
        for(int t=0;t<8;t++){
            int k = lane + 32*t;
            float x = (v[t]-mu)*rinv*sg[k] + sbb[k];
            x = fmaxf(x, 0.f);
            acc += x * sw2[k];
        }
        acc = warpSum(acc);
        if(lane==0) out[(size_t)r*Pdim + p] = acc + rb2;
    }
}

// ---------------- launch ----------------
extern "C" void kernel_launch(void* const* d_in, const int* in_sizes, int n_in,
                              void* d_out, int out_size){
    const float* seq     = (const float*)d_in[0];
    const int*   est     = (const int*)  d_in[1];
    const int*   elen    = (const int*)  d_in[2];
    const int*   ebat    = (const int*)  d_in[3];
    const int*   ei      = (const int*)  d_in[4];
    const int*   pidx    = (const int*)  d_in[5];
    const float* W1      = (const float*)d_in[6];
    const float* a_src1  = (const float*)d_in[7];
    const float* a_dst1  = (const float*)d_in[8];
    const float* b1      = (const float*)d_in[9];
    const float* W2      = (const float*)d_in[10];
    const float* a_src2  = (const float*)d_in[11];
    const float* a_dst2  = (const float*)d_in[12];
    const float* b2      = (const float*)d_in[13];
    const float* relW1   = (const float*)d_in[14];
    const float* relb1   = (const float*)d_in[15];
    const float* ln_g    = (const float*)d_in[16];
    const float* ln_b    = (const float*)d_in[17];
    const float* relW2   = (const float*)d_in[18];
    const float* relb2   = (const float*)d_in[19];
    const float* nerW1   = (const float*)d_in[20];
    const float* nerb1   = (const float*)d_in[21];
    const float* nerW2   = (const float*)d_in[22];
    const float* nerb2   = (const float*)d_in[23];
    float* out = (float*)d_out;

    float *h1p, *h2pp, *es1p, *ed1p, *es2p, *ed2p, *tbp, *nhp;
    cudaGetSymbolAddress((void**)&h1p,  g_h1);
    cudaGetSymbolAddress((void**)&h2pp, g_h2p);
    cudaGetSymbolAddress((void**)&es1p, g_es1);
    cudaGetSymbolAddress((void**)&ed1p, g_ed1);
    cudaGetSymbolAddress((void**)&es2p, g_es2);
    cudaGetSymbolAddress((void**)&ed2p, g_ed2);
    cudaGetSymbolAddress((void**)&tbp,  g_tb);
    cudaGetSymbolAddress((void**)&nhp,  g_nerhid);
    __nv_bfloat16 *sqh,*sql,*x0h,*x0l,*o1h,*o1l,*x2h,*x2l,*w1h,*w1l,*wnh,*wnl,*w2h,*w2l,*wrh,*wrl;
    cudaGetSymbolAddress((void**)&sqh, g_sqh); cudaGetSymbolAddress((void**)&sql, g_sql);
    cudaGetSymbolAddress((void**)&x0h, g_x0h); cudaGetSymbolAddress((void**)&x0l, g_x0l);
    cudaGetSymbolAddress((void**)&o1h, g_o1h); cudaGetSymbolAddress((void**)&o1l, g_o1l);
    cudaGetSymbolAddress((void**)&x2h, g_x2h); cudaGetSymbolAddress((void**)&x2l, g_x2l);
    cudaGetSymbolAddress((void**)&w1h, g_w1h); cudaGetSymbolAddress((void**)&w1l, g_w1l);
    cudaGetSymbolAddress((void**)&wnh, g_wnh); cudaGetSymbolAddress((void**)&wnl, g_wnl);
    cudaGetSymbolAddress((void**)&w2h, g_w2h); cudaGetSymbolAddress((void**)&w2l, g_w2l);
    cudaGetSymbolAddress((void**)&wrh, g_wrh); cudaGetSymbolAddress((void**)&wrl, g_wrl);
    int *p_es1 = (int*)es1p; (void)p_es1;

    static cudaStream_t sNER = nullptr, sIDX = nullptr, sWSP = nullptr;
    static cudaEvent_t evRoot, evNER, evIDX, evW1, evW2, evREL;
    if(sNER == nullptr){
        cudaStreamCreateWithFlags(&sNER, cudaStreamNonBlocking);
        cudaStreamCreateWithFlags(&sIDX, cudaStreamNonBlocking);
        cudaStreamCreateWithFlags(&sWSP, cudaStreamNonBlocking);
        cudaEventCreateWithFlags(&evRoot, cudaEventDisableTiming);
        cudaEventCreateWithFlags(&evNER,  cudaEventDisableTiming);
        cudaEventCreateWithFlags(&evIDX,  cudaEventDisableTiming);
        cudaEventCreateWithFlags(&evW1,   cudaEventDisableTiming);
        cudaEventCreateWithFlags(&evW2,   cudaEventDisableTiming);
        cudaEventCreateWithFlags(&evREL,  cudaEventDisableTiming);
        cudaFuncSetAttribute(k_hmma, cudaFuncAttributeMaxDynamicSharedMemorySize, HMMA_SMEM);
    }

    #define SPLIT(st, src, dh, dl, cnt) \
        k_split<<<((cnt)/4 + 255)/256, 256, 0, st>>>((const float4*)(src), (uint2*)(dh), (uint2*)(dl), (cnt)/4)

    // fork
    cudaEventRecord(evRoot, 0);
    cudaStreamWaitEvent(sNER, evRoot, 0);
    cudaStreamWaitEvent(sIDX, evRoot, 0);
    cudaStreamWaitEvent(sWSP, evRoot, 0);

    // --- NER chain (independent) ---
    SPLIT(sNER, nerW1, wnh, wnl, Hdim*NERH);
    SPLIT(sNER, seq,   sqh, sql, NERROWS*Hdim);
    k_hmma<<<dim3(NERH/128, NERROWS/128, 1), 256, HMMA_SMEM, sNER>>>(
        sqh, sql, Hdim, wnh, wnl, NERH, 0, nerb1, 1, nhp, NERH, 0);
    k_ner2<<<NERROWS/8, 256, 0, sNER>>>(nhp, nerW2, nerb2, out);
    cudaEventRecord(evNER, sNER);

    // --- index build chain (CSR + pair sort) ---
    k_idx_init<<<(Ndim+255)/256, 256, 0, sIDX>>>();
    k_csr_count<<<(ETOT+255)/256, 256, 0, sIDX>>>(ei);
    k_pair_count<<<(Pdim+255)/256, 256, 0, sIDX>>>(pidx);
    {
        int *degp, *rowp, *pdegp, *prowp;
        cudaGetSymbolAddress((void**)&degp, g_deg);
        cudaGetSymbolAddress((void**)&rowp, g_rowstart);
        cudaGetSymbolAddress((void**)&pdegp, g_pdeg);
        cudaGetSymbolAddress((void**)&prowp, g_prow);
        k_scan4096<<<1, 1024, 0, sIDX>>>(degp, rowp);
        k_scan4096<<<1, 1024, 0, sIDX>>>(pdegp, prowp);
    }
    k_csr_scatter<<<(ETOT+255)/256, 256, 0, sIDX>>>(ei);
    k_pair_scatter<<<(Pdim+255)/256, 256, 0, sIDX>>>(pidx);
    cudaEventRecord(evIDX, sIDX);

    // --- weight splits ---
    SPLIT(sWSP, W1, w1h, w1l, Hdim*F1);
    cudaEventRecord(evW1, sWSP);
    k_split_padW2<<<F1*128/256, 256, 0, sWSP>>>(W2, w2h, w2l);
    cudaEventRecord(evW2, sWSP);
    SPLIT(sWSP, relW1, wrh, wrl, 12*C2*RHID);
    cudaEventRecord(evREL, sWSP);

    // --- main GAT chain (default stream) ---
    k_span_pool<<<Ndim, 192>>>(seq, est, elen, ebat, x0h, x0l);
    cudaStreamWaitEvent(0, evW1, 0);
    k_hmma<<<dim3(F1/128, Ndim/128, 1), 256, HMMA_SMEM>>>(
        x0h, x0l, Hdim, w1h, w1l, F1, 0, nullptr, 0, h1p, F1, 0);
    k_attn_coef<H1, C1, F1><<<Ndim, 128>>>(h1p, a_src1, a_dst1, es1p, ed1p);
    cudaStreamWaitEvent(0, evIDX, 0);
    k_gat_agg<H1, C1, F1, true, true><<<Ndim, 128>>>(h1p, es1p, ed1p, b1, nullptr, o1h, o1l);
    cudaStreamWaitEvent(0, evW2, 0);
    k_hmma<<<dim3(1, Ndim/128, 1), 256, HMMA_SMEM>>>(
        o1h, o1l, F1, w2h, w2l, 128, 0, nullptr, 0, h2pp, 128, 0);
    k_attn_coef<1, C2, 128><<<Ndim, 32>>>(h2pp, a_src2, a_dst2, es2p, ed2p);
    k_gat_agg<1, C2, 128, false, true><<<Ndim, 32>>>(h2pp, es2p, ed2p, b2, nullptr, x2h, x2l);
    cudaStreamWaitEvent(0, evREL, 0);
    k_hmma<<<dim3(RHID/128, Ndim/128, 12), 256, HMMA_SMEM>>>(
        x2h, x2l, C2, wrh, wrl, RHID, (long)C2*RHID, nullptr, 0,
        tbp, RHID, (long)Ndim*RHID);
    k_rel_g<<<dim3(Ndim, NREL), 256>>>(pidx, relb1, ln_g, ln_b, relW2, relb2, out + NER_OUT_ELEMS);

    // join
    cudaStreamWaitEvent(0, evNER, 0);
    #undef SPLIT
}

// round 6
// speedup vs baseline: 2.0557x; 1.0590x over previous
#include <cuda_runtime.h>
#include <cuda_bf16.h>
#include <math.h>
#include <stdint.h>

// ---------------- problem constants ----------------
#define Bdim 32
#define Sdim 512
#define Hdim 768
#define Ndim 4096
#define Edim 131072
#define Pdim 65536
#define ETOT (Edim + Ndim)
#define H1 4
#define C1 128
#define F1 (H1*C1)               // 512
#define C2 64
#define NREL 6
#define RHID 256
#define NERH 256
#define NERL 9
#define SLOPE 0.2f
#define LNEPS 1e-5f
#define NER_OUT_ELEMS (Bdim*Sdim*NERL)
#define NERROWS (Bdim*Sdim)      // 16384

// ---------------- device scratch ----------------
__device__ float g_h1[Ndim*F1];
__device__ float g_h2p[Ndim*128];
__device__ float g_es1[Ndim*H1], g_ed1[Ndim*H1];
__device__ float g_es2[Ndim],    g_ed2[Ndim];
__device__ int   g_deg[Ndim], g_cursor[Ndim], g_rowstart[Ndim+1];
__device__ int   g_csr[ETOT];
__device__ int   g_pdeg[Ndim], g_pcur[Ndim], g_prow[Ndim+1];
__device__ int   g_psorted[Pdim];
__device__ float g_tb[12*Ndim*RHID];
__device__ __nv_bfloat16 g_sqh[NERROWS*Hdim], g_sql[NERROWS*Hdim];
__device__ __nv_bfloat16 g_x0h[Ndim*Hdim],    g_x0l[Ndim*Hdim];
__device__ __nv_bfloat16 g_o1h[Ndim*F1],      g_o1l[Ndim*F1];
__device__ __nv_bfloat16 g_x2h[Ndim*C2],      g_x2l[Ndim*C2];
__device__ __nv_bfloat16 g_w1h[Hdim*F1],      g_w1l[Hdim*F1];
__device__ __nv_bfloat16 g_wnh[Hdim*NERH],    g_wnl[Hdim*NERH];
__device__ __nv_bfloat16 g_w2h[F1*128],       g_w2l[F1*128];
__device__ __nv_bfloat16 g_wrh[12*C2*RHID],   g_wrl[12*C2*RHID];

// ---------------- helpers ----------------
__device__ __forceinline__ float warpSum(float v){
    #pragma unroll
    for(int o=16;o;o>>=1) v += __shfl_xor_sync(0xffffffffu, v, o);
    return v;
}
__device__ __forceinline__ float warpMax(float v){
    #pragma unroll
    for(int o=16;o;o>>=1) v = fmaxf(v, __shfl_xor_sync(0xffffffffu, v, o));
    return v;
}
__device__ __forceinline__ float quadSum(float v){
    v += __shfl_xor_sync(0xffffffffu, v, 1);
    v += __shfl_xor_sync(0xffffffffu, v, 2);
    return v;
}
__device__ __forceinline__ uint32_t smem_u32(const void* p){
    uint32_t a;
    asm("{ .reg .u64 t; cvta.to.shared.u64 t, %1; cvt.u32.u64 %0, t; }" : "=r"(a) : "l"(p));
    return a;
}
__device__ __forceinline__ unsigned pack_bf2(__nv_bfloat16 a, __nv_bfloat16 b){
    __nv_bfloat162 t; t.x = a; t.y = b;
    return *reinterpret_cast<unsigned*>(&t);
}
__device__ __forceinline__ void cp16(uint32_t dst, const void* src){
    asm volatile("cp.async.ca.shared.global [%0], [%1], 16;" :: "r"(dst), "l"(src) : "memory");
}
__device__ __forceinline__ void ldsm4(uint32_t* r, uint32_t addr){
    asm volatile("ldmatrix.sync.aligned.m8n8.x4.shared.b16 {%0,%1,%2,%3}, [%4];"
        : "=r"(r[0]), "=r"(r[1]), "=r"(r[2]), "=r"(r[3]) : "r"(addr));
}
__device__ __forceinline__ void ldsm4t(uint32_t* r, uint32_t addr){
    asm volatile("ldmatrix.sync.aligned.m8n8.x4.trans.shared.b16 {%0,%1,%2,%3}, [%4];"
        : "=r"(r[0]), "=r"(r[1]), "=r"(r[2]), "=r"(r[3]) : "r"(addr));
}
__device__ __forceinline__ void mma16816(float* d, const uint32_t* a, uint32_t b0, uint32_t b1){
    asm volatile(
        "mma.sync.aligned.m16n8k16.row.col.f32.bf16.bf16.f32 "
        "{%0,%1,%2,%3}, {%4,%5,%6,%7}, {%8,%9}, {%0,%1,%2,%3};"
        : "+f"(d[0]), "+f"(d[1]), "+f"(d[2]), "+f"(d[3])
        : "r"(a[0]), "r"(a[1]), "r"(a[2]), "r"(a[3]), "r"(b0), "r"(b1));
}

// ---------------- split fp32 -> bf16 hi/lo planes ----------------
__global__ void k_split(const float4* __restrict__ in, uint2* __restrict__ hi,
                        uint2* __restrict__ lo, int n4){
    int i = blockIdx.x*blockDim.x + threadIdx.x;
    if(i >= n4) return;
    float4 v = in[i];
    __nv_bfloat16 h0=__float2bfloat16(v.x), h1=__float2bfloat16(v.y);
    __nv_bfloat16 h2=__float2bfloat16(v.z), h3=__float2bfloat16(v.w);
    __nv_bfloat16 l0=__float2bfloat16(v.x-__bfloat162float(h0));
    __nv_bfloat16 l1=__float2bfloat16(v.y-__bfloat162float(h1));
    __nv_bfloat16 l2=__float2bfloat16(v.z-__bfloat162float(h2));
    __nv_bfloat16 l3=__float2bfloat16(v.w-__bfloat162float(h3));
    hi[i] = make_uint2(pack_bf2(h0,h1), pack_bf2(h2,h3));
    lo[i] = make_uint2(pack_bf2(l0,l1), pack_bf2(l2,l3));
}

__global__ void k_split_padW2(const float* __restrict__ W2,
                              __nv_bfloat16* __restrict__ hi, __nv_bfloat16* __restrict__ lo){
    int idx = blockIdx.x*256 + threadIdx.x;
    int k = idx >> 7, c = idx & 127;
    float v = (c < C2) ? W2[k*C2 + c] : 0.f;
    __nv_bfloat16 h = __float2bfloat16(v);
    __nv_bfloat16 l = __float2bfloat16(v - __bfloat162float(h));
    hi[idx] = h; lo[idx] = l;
}

// ---------------- split-bf16 HMMA GEMM with fused epilogues ----------------
// EPI: 0 = store only; 1 = store + attention coef atomics; 2 = NER stage2 (no store)
#define SA 40
#define SB 136
#define A_PL (128*SA*2)
#define B_PL (32*SB*2)
#define BOFF (2*A_PL)
#define STAGE_SZ (BOFF + 2*B_PL)
#define PIPE_SZ (2*STAGE_SZ)         // 75776
#define HMMA_SMEM (PIPE_SZ + 4608)   // + epilogue extras
template<int EPI>
__global__ void __launch_bounds__(256) k_hmma(
        const __nv_bfloat16* __restrict__ aHi, const __nv_bfloat16* __restrict__ aLo, int K,
        const __nv_bfloat16* __restrict__ wHi, const __nv_bfloat16* __restrict__ wLo, int N,
        long wStrideZ, const float* __restrict__ bias, int reluFlag,
        float* __restrict__ C, int ldc, long cStrideZ,
        const float* __restrict__ p1, const float* __restrict__ p2,
        float* __restrict__ q1, float* __restrict__ q2,
        int headC, int nheads, int validN){
    extern __shared__ char sm_buf[];
    int tid = threadIdx.x, lane = tid & 31, warp = tid >> 5;
    int wm = warp & 1, wn = warp >> 1;
    int grp = lane >> 3, rr = lane & 7;
    int arow = rr + (grp & 1)*8;
    int acol = (grp >> 1)*8;

    int n0 = blockIdx.x*128, m0 = blockIdx.y*128, z = blockIdx.z;
    const __nv_bfloat16* wzh = wHi + (size_t)z*wStrideZ;
    const __nv_bfloat16* wzl = wLo + (size_t)z*wStrideZ;
    int nc = K >> 5;

    float* sx = (float*)(sm_buf + PIPE_SZ);
    if(EPI == 1){
        if(tid < 128){
            int n = n0 + tid;
            sx[tid]     = (n < validN) ? p1[n] : 0.f;
            sx[128+tid] = (n < validN) ? p2[n] : 0.f;
        }
    }else if(EPI == 2){
        for(int j=tid; j<128*NERL; j+=256)
            sx[j] = p1[(size_t)(n0 + j/NERL)*NERL + (j%NERL)];
    }

    float acc[4][4][4];
    #pragma unroll
    for(int a=0;a<4;a++)
        #pragma unroll
        for(int b=0;b<4;b++)
            #pragma unroll
            for(int c=0;c<4;c++) acc[a][b][c] = 0.f;

    uint32_t sb0 = smem_u32(sm_buf);

    #define ISSUE(kc, st) do{                                                        \
        uint32_t sb = sb0 + (st)*STAGE_SZ;                                           \
        _Pragma("unroll")                                                            \
        for(int i=0;i<2;i++){                                                        \
            int idx = tid + i*256; int row = idx >> 2, k8 = idx & 3;                 \
            size_t go = (size_t)(m0+row)*K + (kc)*32 + k8*8;                         \
            uint32_t d = sb + row*80 + k8*16;                                        \
            cp16(d,        aHi + go);                                                \
            cp16(d + A_PL, aLo + go);                                                \
        }                                                                            \
        _Pragma("unroll")                                                            \
        for(int i=0;i<2;i++){                                                        \
            int idx = tid + i*256; int kr = idx >> 4, ncol = idx & 15;               \
            size_t go = (size_t)((kc)*32 + kr)*N + n0 + ncol*8;                      \
            uint32_t d = sb + BOFF + kr*272 + ncol*16;                               \
            cp16(d,        wzh + go);                                                \
            cp16(d + B_PL, wzl + go);                                                \
        }                                                                            \
        asm volatile("cp.async.commit_group;" ::: "memory");                         \
    }while(0)

    ISSUE(0, 0);
    for(int kc=0; kc<nc; kc++){
        if(kc+1 < nc){
            ISSUE(kc+1, (kc+1)&1);
            asm volatile("cp.async.wait_group 1;" ::: "memory");
        }else{
            asm volatile("cp.async.wait_group 0;" ::: "memory");
        }
        __syncthreads();
        uint32_t sb = sb0 + (kc&1)*STAGE_SZ;
        uint32_t aBase = sb + ((wm*64 + arow)*SA + acol)*2;
        uint32_t bBase = sb + BOFF + (arow*SB + wn*32 + acol)*2;
        #pragma unroll
        for(int kk=0; kk<2; kk++){
            uint32_t af[4][2][4];
            #pragma unroll
            for(int mt=0; mt<4; mt++){
                uint32_t ad = aBase + mt*(16*SA*2) + kk*32;
                ldsm4(af[mt][0], ad);
                ldsm4(af[mt][1], ad + A_PL);
            }
            uint32_t bfr[2][2][4];
            #pragma unroll
            for(int pr=0; pr<2; pr++){
                uint32_t bd = bBase + kk*(16*SB*2) + pr*32;
                ldsm4t(bfr[pr][0], bd);
                ldsm4t(bfr[pr][1], bd + B_PL);
            }
            #pragma unroll
            for(int mt=0; mt<4; mt++)
                #pragma unroll
                for(int nt=0; nt<4; nt++){
                    int pr = nt >> 1, hf = (nt & 1)*2;
                    uint32_t bh0 = bfr[pr][0][hf], bh1 = bfr[pr][0][hf+1];
                    uint32_t bl0 = bfr[pr][1][hf], bl1 = bfr[pr][1][hf+1];
                    mma16816(acc[mt][nt], af[mt][0], bh0, bh1);
                    mma16816(acc[mt][nt], af[mt][0], bl0, bl1);
                    mma16816(acc[mt][nt], af[mt][1], bh0, bh1);
                }
        }
        __syncthreads();
    }
    #undef ISSUE

    // ---- epilogue ----
    float* Cz = C + (size_t)z*cStrideZ;
    int hh = (n0 + wn*32) / headC;
    bool hhok = hh < nheads;
    // per-thread column bias (same for every row)
    float bcol[8];
    #pragma unroll
    for(int nt=0; nt<4; nt++){
        int n = n0 + wn*32 + nt*8 + (lane & 3)*2;
        bcol[nt*2]   = bias ? bias[n]   : 0.f;
        bcol[nt*2+1] = bias ? bias[n+1] : 0.f;
    }
    #pragma unroll
    for(int mt=0; mt<4; mt++){
        int mb = m0 + wm*64 + mt*16 + (lane >> 2);
        #pragma unroll
        for(int half=0; half<2; half++){
            int m = mb + half*8;
            float v[8];
            #pragma unroll
            for(int nt=0; nt<4; nt++){
                float a0 = acc[mt][nt][half*2]   + bcol[nt*2];
                float a1 = acc[mt][nt][half*2+1] + bcol[nt*2+1];
                if(reluFlag){ a0 = fmaxf(a0,0.f); a1 = fmaxf(a1,0.f); }
                v[nt*2] = a0; v[nt*2+1] = a1;
                if(EPI != 2){
                    int n = n0 + wn*32 + nt*8 + (lane & 3)*2;
                    *reinterpret_cast<float2*>(Cz + (size_t)m*ldc + n) = make_float2(a0, a1);
                }
            }
            if(EPI == 1){
                float ps = 0.f, pd = 0.f;
                #pragma unroll
                for(int t=0;t<8;t++){
                    int ln = wn*32 + (t>>1)*8 + (lane&3)*2 + (t&1);
                    ps += v[t]*sx[ln];
                    pd += v[t]*sx[128+ln];
                }
                ps = quadSum(ps); pd = quadSum(pd);
                if((lane&3)==0 && hhok){
                    atomicAdd(&q1[m*nheads + hh], ps);
                    atomicAdd(&q2[m*nheads + hh], pd);
                }
            }else if(EPI == 2){
                float pc[NERL];
                #pragma unroll
                for(int c=0;c<NERL;c++) pc[c] = 0.f;
                #pragma unroll
                for(int t=0;t<8;t++){
                    int ln = wn*32 + (t>>1)*8 + (lane&3)*2 + (t&1);
                    #pragma unroll
                    for(int c=0;c<NERL;c++) pc[c] += v[t]*sx[ln*NERL + c];
                }
                #pragma unroll
                for(int c=0;c<NERL;c++){
                    float s = quadSum(pc[c]);
                    if((lane&3)==0) atomicAdd(&q1[(size_t)m*NERL + c], s);
                }
            }
        }
    }
}

// ---------------- entity span mean pooling -> bf16 hi/lo planes ----------------
__global__ void k_span_pool(const float* __restrict__ seq,
                            const int* __restrict__ est, const int* __restrict__ elen,
                            const int* __restrict__ ebat,
                            __nv_bfloat16* __restrict__ xh, __nv_bfloat16* __restrict__ xl){
    int n = blockIdx.x;
    int b = ebat[n], st = est[n], len = elen[n];
    const float* base = seq + ((size_t)b*Sdim + st)*Hdim + threadIdx.x*4;
    float4 acc = make_float4(0.f,0.f,0.f,0.f);
    for(int r=0; r<=len; r++){
        float4 t = *reinterpret_cast<const float4*>(base + (size_t)r*Hdim);
        acc.x += t.x; acc.y += t.y; acc.z += t.z; acc.w += t.w;
    }
    float inv = 1.0f/(float)(len+1);
    acc.x*=inv; acc.y*=inv; acc.z*=inv; acc.w*=inv;
    __nv_bfloat16 h0=__float2bfloat16(acc.x), h1=__float2bfloat16(acc.y);
    __nv_bfloat16 h2=__float2bfloat16(acc.z), h3=__float2bfloat16(acc.w);
    __nv_bfloat16 l0=__float2bfloat16(acc.x-__bfloat162float(h0));
    __nv_bfloat16 l1=__float2bfloat16(acc.y-__bfloat162float(h1));
    __nv_bfloat16 l2=__float2bfloat16(acc.z-__bfloat162float(h2));
    __nv_bfloat16 l3=__float2bfloat16(acc.w-__bfloat162float(h3));
    size_t o = (size_t)n*Hdim + threadIdx.x*4;
    *reinterpret_cast<uint2*>(&xh[o]) = make_uint2(pack_bf2(h0,h1), pack_bf2(h2,h3));
    *reinterpret_cast<uint2*>(&xl[o]) = make_uint2(pack_bf2(l0,l1), pack_bf2(l2,l3));
}

// ---------------- init kernels ----------------
__global__ void k_init0(){
    int i = blockIdx.x*blockDim.x + threadIdx.x;
    if(i >= Ndim) return;
    g_deg[i]=0; g_cursor[i]=0; g_pdeg[i]=0; g_pcur[i]=0;
    g_es2[i]=0.f; g_ed2[i]=0.f;
    #pragma unroll
    for(int h=0;h<H1;h++){ g_es1[i*H1+h]=0.f; g_ed1[i*H1+h]=0.f; }
}
__global__ void k_out_init(const float* __restrict__ b2, float* __restrict__ out){
    int i = blockIdx.x*blockDim.x + threadIdx.x;
    if(i < NER_OUT_ELEMS) out[i] = b2[i % NERL];
}

// ---------------- merged CSR + pair-sort build ----------------
__global__ void k_count(const int* __restrict__ ei, const int* __restrict__ pidx){
    int idx = blockIdx.x*blockDim.x + threadIdx.x;
    if(idx < ETOT){
        int dst = (idx < Edim) ? ei[Edim + idx] : (idx - Edim);
        atomicAdd(&g_deg[dst], 1);
    }else if(idx < ETOT + Pdim){
        atomicAdd(&g_pdeg[pidx[(idx - ETOT)*2]], 1);
    }
}
__global__ void k_scan(){
    __shared__ int s[1024];
    const int* deg = (blockIdx.x == 0) ? g_deg : g_pdeg;
    int* rowstart  = (blockIdx.x == 0) ? g_rowstart : g_prow;
    int t = threadIdx.x;
    int v0 = deg[t*4+0], v1 = deg[t*4+1], v2 = deg[t*4+2], v3 = deg[t*4+3];
    int c0 = v0, c1 = c0+v1, c2 = c1+v2, c3 = c2+v3;
    s[t] = c3;
    __syncthreads();
    for(int off=1; off<1024; off<<=1){
        int x = (t >= off) ? s[t-off] : 0;
        __syncthreads();
        s[t] += x;
        __syncthreads();
    }
    int excl = s[t] - c3;
    rowstart[t*4+1] = excl + c0;
    rowstart[t*4+2] = excl + c1;
    rowstart[t*4+3] = excl + c2;
    rowstart[t*4+4] = excl + c3;
    if(t==0) rowstart[0] = 0;
}
__global__ void k_scatter(const int* __restrict__ ei, const int* __restrict__ pidx){
    int idx = blockIdx.x*blockDim.x + threadIdx.x;
    if(idx < ETOT){
        int src, dst;
        if(idx < Edim){ src = ei[idx]; dst = ei[Edim + idx]; }
        else          { src = idx - Edim; dst = src; }
        int pos = g_rowstart[dst] + atomicAdd(&g_cursor[dst], 1);
        g_csr[pos] = src;
    }else if(idx < ETOT + Pdim){
        int p = idx - ETOT;
        int i = pidx[p*2];
        int pos = g_prow[i] + atomicAdd(&g_pcur[i], 1);
        g_psorted[pos] = p;
    }
}

// ---------------- GAT softmax + aggregation ----------------
template<int HEADS,int C,int LD,bool RELU,bool SPLIT>
__global__ void k_gat_agg(const float* __restrict__ h,
                          const float* __restrict__ es, const float* __restrict__ ed,
                          const float* __restrict__ bias, float* __restrict__ out,
                          __nv_bfloat16* __restrict__ outH, __nv_bfloat16* __restrict__ outL){
    const int F = HEADS*C;
    int d = blockIdx.x;
    int hh = threadIdx.x >> 5, lane = threadIdx.x & 31;
    int rs = g_rowstart[d], re = g_rowstart[d+1];
    float edv = ed[d*HEADS + hh];

    float m = -1e30f;
    for(int e=rs+lane; e<re; e+=32){
        int s = g_csr[e];
        float t = es[s*HEADS+hh] + edv;
        t = (t > 0.f) ? t : SLOPE*t;
        m = fmaxf(m, t);
    }
    m = warpMax(m);

    float den = 0.f;
    for(int e=rs+lane; e<re; e+=32){
        int s = g_csr[e];
        float t = es[s*HEADS+hh] + edv;
        t = (t > 0.f) ? t : SLOPE*t;
        den += __expf(t - m);
    }
    den = warpSum(den);
    float inv = 1.0f/den;

    float acc[C/32];
    #pragma unroll
    for(int i=0;i<C/32;i++) acc[i]=0.f;

    for(int e=rs; e<re; e++){
        int s = g_csr[e];
        float t = es[s*HEADS+hh] + edv;
        t = (t > 0.f) ? t : SLOPE*t;
        float w = __expf(t - m)*inv;
        const float* hp = h + (size_t)s*LD + hh*C + lane;
        #pragma unroll
        for(int i=0;i<C/32;i++) acc[i] += w*hp[32*i];
    }
    #pragma unroll
    for(int i=0;i<C/32;i++){
        float v = acc[i] + bias[hh*C + lane + 32*i];
        if(RELU) v = fmaxf(v, 0.f);
        size_t o = (size_t)d*F + hh*C + lane + 32*i;
        if(SPLIT){
            __nv_bfloat16 hb = __float2bfloat16(v);
            outH[o] = hb;
            outL[o] = __float2bfloat16(v - __bfloat162float(hb));
        }else{
            out[o] = v;
        }
    }
}

// ---------------- fused relation head: warp-per-left-entity ----------------
__global__ void k_rel_g(const int* __restrict__ pidx,
                        const float* __restrict__ relb1, const float* __restrict__ lng,
                        const float* __restrict__ lnb, const float* __restrict__ relW2,
                        const float* __restrict__ relb2, float* __restrict__ out){
    __shared__ float sb1[256], sg[256], sbb[256], sw2[256];
    int r = blockIdx.y;
    int tid = threadIdx.x;
    sb1[tid] = relb1[r*256+tid];
    sg[tid]  = lng[r*256+tid];
    sbb[tid] = lnb[r*256+tid];
    sw2[tid] = relW2[r*256+tid];
    __syncthreads();

    int w = tid >> 5, lane = tid & 31;
    int i = blockIdx.x*8 + w;
    int rs = g_prow[i], re = g_prow[i+1];
    if(rs == re) return;
    float rb2 = relb2[r];

    float ti[8];
    const float* tip = g_tb + ((size_t)(r*2)*Ndim + i)*RHID;
    #pragma unroll
    for(int t=0;t<8;t++) ti[t] = tip[lane + 32*t];

    for(int idx = rs; idx < re; idx++){
        int p = g_psorted[idx];
        int j = pidx[p*2+1];
        const float* tj = g_tb + ((size_t)(r*2+1)*Ndim + j)*RHID;
        float v[8]; float s1 = 0.f, s2 = 0.f;
        #pragma unroll
        for(int t=0;t<8;t++){
            int k = lane + 32*t;
            float x = ti[t] + tj[k] + sb1[k];
            v[t] = x; s1 += x; s2 += x*x;
        }
        s1 = warpSum(s1); s2 = warpSum(s2);
        float mu  = s1 * (1.0f/256.0f);
        float var = s2 * (1.0f/256.0f) - mu*mu;
        float rinv = rsqrtf(var + LNEPS);
        float acc = 0.f;
        #pragma unroll
        for(int t=0;t<8;t++){
            int k = lane + 32*t;
            float x = (v[t]-mu)*rinv*sg[k] + sbb[k];
            x = fmaxf(x, 0.f);
            acc += x * sw2[k];
        }
        acc = warpSum(acc);
        if(lane==0) out[(size_t)r*Pdim + p] = acc + rb2;
    }
}

// ---------------- launch ----------------
extern "C" void kernel_launch(void* const* d_in, const int* in_sizes, int n_in,
                              void* d_out, int out_size){
    const float* seq     = (const float*)d_in[0];
    const int*   est     = (const int*)  d_in[1];
    const int*   elen    = (const int*)  d_in[2];
    const int*   ebat    = (const int*)  d_in[3];
    const int*   ei      = (const int*)  d_in[4];
    const int*   pidx    = (const int*)  d_in[5];
    const float* W1      = (const float*)d_in[6];
    const float* a_src1  = (const float*)d_in[7];
    const float* a_dst1  = (const float*)d_in[8];
    const float* b1      = (const float*)d_in[9];
    const float* W2      = (const float*)d_in[10];
    const float* a_src2  = (const float*)d_in[11];
    const float* a_dst2  = (const float*)d_in[12];
    const float* b2      = (const float*)d_in[13];
    const float* relW1   = (const float*)d_in[14];
    const float* relb1   = (const float*)d_in[15];
    const float* ln_g    = (const float*)d_in[16];
    const float* ln_b    = (const float*)d_in[17];
    const float* relW2   = (const float*)d_in[18];
    const float* relb2   = (const float*)d_in[19];
    const float* nerW1   = (const float*)d_in[20];
    const float* nerb1   = (const float*)d_in[21];
    const float* nerW2   = (const float*)d_in[22];
    const float* nerb2   = (const float*)d_in[23];
    float* out = (float*)d_out;

    float *h1p, *h2pp, *es1p, *ed1p, *es2p, *ed2p, *tbp;
    cudaGetSymbolAddress((void**)&h1p,  g_h1);
    cudaGetSymbolAddress((void**)&h2pp, g_h2p);
    cudaGetSymbolAddress((void**)&es1p, g_es1);
    cudaGetSymbolAddress((void**)&ed1p, g_ed1);
    cudaGetSymbolAddress((void**)&es2p, g_es2);
    cudaGetSymbolAddress((void**)&ed2p, g_ed2);
    cudaGetSymbolAddress((void**)&tbp,  g_tb);
    __nv_bfloat16 *sqh,*sql,*x0h,*x0l,*o1h,*o1l,*x2h,*x2l,*w1h,*w1l,*wnh,*wnl,*w2h,*w2l,*wrh,*wrl;
    cudaGetSymbolAddress((void**)&sqh, g_sqh); cudaGetSymbolAddress((void**)&sql, g_sql);
    cudaGetSymbolAddress((void**)&x0h, g_x0h); cudaGetSymbolAddress((void**)&x0l, g_x0l);
    cudaGetSymbolAddress((void**)&o1h, g_o1h); cudaGetSymbolAddress((void**)&o1l, g_o1l);
    cudaGetSymbolAddress((void**)&x2h, g_x2h); cudaGetSymbolAddress((void**)&x2l, g_x2l);
    cudaGetSymbolAddress((void**)&w1h, g_w1h); cudaGetSymbolAddress((void**)&w1l, g_w1l);
    cudaGetSymbolAddress((void**)&wnh, g_wnh); cudaGetSymbolAddress((void**)&wnl, g_wnl);
    cudaGetSymbolAddress((void**)&w2h, g_w2h); cudaGetSymbolAddress((void**)&w2l, g_w2l);
    cudaGetSymbolAddress((void**)&wrh, g_wrh); cudaGetSymbolAddress((void**)&wrl, g_wrl);

    static cudaStream_t sNER = nullptr, sIDX = nullptr, sWSP = nullptr;
    static cudaEvent_t evRoot, evNER, evIDX, evZERO, evW1, evW2, evREL;
    if(sNER == nullptr){
        cudaStreamCreateWithFlags(&sNER, cudaStreamNonBlocking);
        cudaStreamCreateWithFlags(&sIDX, cudaStreamNonBlocking);
        cudaStreamCreateWithFlags(&sWSP, cudaStreamNonBlocking);
        cudaEventCreateWithFlags(&evRoot, cudaEventDisableTiming);
        cudaEventCreateWithFlags(&evNER,  cudaEventDisableTiming);
        cudaEventCreateWithFlags(&evIDX,  cudaEventDisableTiming);
        cudaEventCreateWithFlags(&evZERO, cudaEventDisableTiming);
        cudaEventCreateWithFlags(&evW1,   cudaEventDisableTiming);
        cudaEventCreateWithFlags(&evW2,   cudaEventDisableTiming);
        cudaEventCreateWithFlags(&evREL,  cudaEventDisableTiming);
        cudaFuncSetAttribute(k_hmma<0>, cudaFuncAttributeMaxDynamicSharedMemorySize, HMMA_SMEM);
        cudaFuncSetAttribute(k_hmma<1>, cudaFuncAttributeMaxDynamicSharedMemorySize, HMMA_SMEM);
        cudaFuncSetAttribute(k_hmma<2>, cudaFuncAttributeMaxDynamicSharedMemorySize, HMMA_SMEM);
    }

    #define SPLIT(st, src, dh, dl, cnt) \
        k_split<<<((cnt)/4 + 255)/256, 256, 0, st>>>((const float4*)(src), (uint2*)(dh), (uint2*)(dl), (cnt)/4)

    // fork
    cudaEventRecord(evRoot, 0);
    cudaStreamWaitEvent(sNER, evRoot, 0);
    cudaStreamWaitEvent(sIDX, evRoot, 0);
    cudaStreamWaitEvent(sWSP, evRoot, 0);

    // --- NER chain (independent): out init with b2, split, fused GEMM+stage2 ---
    k_out_init<<<(NER_OUT_ELEMS+255)/256, 256, 0, sNER>>>(nerb2, out);
    SPLIT(sNER, nerW1, wnh, wnl, Hdim*NERH);
    SPLIT(sNER, seq,   sqh, sql, NERROWS*Hdim);
    k_hmma<2><<<dim3(NERH/128, NERROWS/128, 1), 256, HMMA_SMEM, sNER>>>(
        sqh, sql, Hdim, wnh, wnl, NERH, 0, nerb1, 1, nullptr, 0, 0,
        nerW2, nullptr, out, nullptr, 128, 1, NERH);
    cudaEventRecord(evNER, sNER);

    // --- index build chain (zero-init + CSR + pair sort) ---
    k_init0<<<(Ndim+255)/256, 256, 0, sIDX>>>();
    cudaEventRecord(evZERO, sIDX);
    k_count<<<(ETOT+Pdim+255)/256, 256, 0, sIDX>>>(ei, pidx);
    k_scan<<<2, 1024, 0, sIDX>>>();
    k_scatter<<<(ETOT+Pdim+255)/256, 256, 0, sIDX>>>(ei, pidx);
    cudaEventRecord(evIDX, sIDX);

    // --- weight splits ---
    SPLIT(sWSP, W1, w1h, w1l, Hdim*F1);
    cudaEventRecord(evW1, sWSP);
    k_split_padW2<<<F1*128/256, 256, 0, sWSP>>>(W2, w2h, w2l);
    cudaEventRecord(evW2, sWSP);
    SPLIT(sWSP, relW1, wrh, wrl, 12*C2*RHID);
    cudaEventRecord(evREL, sWSP);

    // --- main GAT chain ---
    k_span_pool<<<Ndim, 192>>>(seq, est, elen, ebat, x0h, x0l);
    cudaStreamWaitEvent(0, evW1, 0);
    cudaStreamWaitEvent(0, evZERO, 0);
    k_hmma<1><<<dim3(F1/128, Ndim/128, 1), 256, HMMA_SMEM>>>(
        x0h, x0l, Hdim, w1h, w1l, F1, 0, nullptr, 0, h1p, F1, 0,
        a_src1, a_dst1, es1p, ed1p, C1, H1, F1);
    cudaStreamWaitEvent(0, evIDX, 0);
    k_gat_agg<H1, C1, F1, true, true><<<Ndim, 128>>>(h1p, es1p, ed1p, b1, nullptr, o1h, o1l);
    cudaStreamWaitEvent(0, evW2, 0);
    k_hmma<1><<<dim3(1, Ndim/128, 1), 256, HMMA_SMEM>>>(
        o1h, o1l, F1, w2h, w2l, 128, 0, nullptr, 0, h2pp, 128, 0,
        a_src2, a_dst2, es2p, ed2p, C2, 1, C2);
    k_gat_agg<1, C2, 128, false, true><<<Ndim, 32>>>(h2pp, es2p, ed2p, b2, nullptr, x2h, x2l);
    cudaStreamWaitEvent(0, evREL, 0);
    k_hmma<0><<<dim3(RHID/128, Ndim/128, 12), 256, HMMA_SMEM>>>(
        x2h, x2l, C2, wrh, wrl, RHID, (long)C2*RHID, nullptr, 0,
        tbp, RHID, (long)Ndim*RHID,
        nullptr, nullptr, nullptr, nullptr, 128, 1, RHID);
    k_rel_g<<<dim3(Ndim/8, NREL), 256>>>(pidx, relb1, ln_g, ln_b, relW2, relb2, out + NER_OUT_ELEMS);

    // join
    cudaStreamWaitEvent(0, evNER, 0);
    #undef SPLIT
}